// round 2
// baseline (speedup 1.0000x reference)
#include <cuda_runtime.h>
#include <math.h>

#define N_NODES 30000
#define F_IN    256
#define HEADS   4
#define CH      128
#define D_HID   (HEADS * CH)   // 512
#define D_OUT   128
#define E_MAX   480000
#define ET_MAX  (E_MAX + N_NODES)  // 510000

// ---------------- scratch (device globals; no allocations allowed) ----------
__device__ float g_hA[(size_t)N_NODES * D_HID];    // GEMM output (pre-aggregation features)
__device__ float g_hB[(size_t)N_NODES * D_HID];    // layer activation (input to next layer)
__device__ float g_agg[(size_t)N_NODES * D_HID];   // aggregation accumulator
__device__ float g_asrc[N_NODES * HEADS];
__device__ float g_adst[N_NODES * HEADS];
__device__ float g_m[N_NODES * HEADS];
__device__ float g_den[N_NODES * HEADS];
__device__ float g_e[(size_t)ET_MAX * HEADS];

// ---------------- helpers ---------------------------------------------------
__device__ __forceinline__ void atomicMaxF(float* addr, float val) {
    int* ai = (int*)addr;
    int old = *ai;
    while (__int_as_float(old) < val) {
        int assumed = old;
        old = atomicCAS(ai, assumed, __float_as_int(val));
        if (old == assumed) break;
    }
}

__device__ __forceinline__ void redAdd4(float4* ptr, float4 v) {
    asm volatile("red.global.add.v4.f32 [%0], {%1,%2,%3,%4};"
                 :: "l"(ptr), "f"(v.x), "f"(v.y), "f"(v.z), "f"(v.w)
                 : "memory");
}

// edge_index is int32 on device (JAX x64 disabled downgrades int64 -> int32)
__device__ __forceinline__ void edge_sd(int e, const int* __restrict__ ei,
                                        int E, int& s, int& d) {
    if (e < E) { s = ei[e]; d = ei[E + e]; }
    else       { s = d = e - E; }   // self-loops appended
}

// ---------------- GEMM: C[M,N] = A[M,K] @ B[K,N], fp32, row-major ------------
__global__ __launch_bounds__(256)
void gemm_kernel(const float* __restrict__ A, const float* __restrict__ B,
                 float* __restrict__ C, int M, int K, int N) {
    const int BM = 128, BN = 128, BK = 8, TM = 8, TN = 8;
    __shared__ float As[BK][BM];
    __shared__ float Bs[BK][BN];
    int tid = threadIdx.x;
    int bm = blockIdx.y * BM;
    int bn = blockIdx.x * BN;
    int tr = (tid / 16) * TM;
    int tc = (tid % 16) * TN;

    float acc[TM][TN];
#pragma unroll
    for (int i = 0; i < TM; i++)
#pragma unroll
        for (int j = 0; j < TN; j++) acc[i][j] = 0.f;

    for (int k0 = 0; k0 < K; k0 += BK) {
#pragma unroll
        for (int i = 0; i < 4; i++) {
            int idx = tid * 4 + i;            // 0..1023
            int r = idx >> 3, c = idx & 7;    // A tile is BM x BK
            int gr = bm + r;
            float v = 0.f;
            if (gr < M) v = A[(size_t)gr * K + k0 + c];
            As[c][r] = v;
        }
#pragma unroll
        for (int i = 0; i < 4; i++) {
            int idx = tid * 4 + i;
            int r = idx >> 7, c = idx & 127;  // B tile is BK x BN
            Bs[r][c] = B[(size_t)(k0 + r) * N + bn + c];
        }
        __syncthreads();
#pragma unroll
        for (int kk = 0; kk < BK; ++kk) {
            float ra[TM], rb[TN];
#pragma unroll
            for (int i = 0; i < TM; i++) ra[i] = As[kk][tr + i];
#pragma unroll
            for (int j = 0; j < TN; j++) rb[j] = Bs[kk][tc + j];
#pragma unroll
            for (int i = 0; i < TM; i++)
#pragma unroll
                for (int j = 0; j < TN; j++) acc[i][j] += ra[i] * rb[j];
        }
        __syncthreads();
    }
#pragma unroll
    for (int i = 0; i < TM; i++) {
        int gr = bm + tr + i;
        if (gr < M) {
#pragma unroll
            for (int j = 0; j < TN; j++)
                C[(size_t)gr * N + bn + tc + j] = acc[i][j];
        }
    }
}

// ---------------- attention scores: a_src/a_dst[n,h] = <h[n,h,:], att[h,:]> --
__global__ void attn_kernel(const float* __restrict__ h,
                            const float* __restrict__ att_s,
                            const float* __restrict__ att_d,
                            float* __restrict__ asrc, float* __restrict__ adst,
                            int N, int H, int C) {
    int w = (blockIdx.x * blockDim.x + threadIdx.x) >> 5;
    int lane = threadIdx.x & 31;
    if (w >= N * H) return;
    int n = w / H, hh = w - n * H;
    const float* hp = h + ((size_t)n * H + hh) * C;
    float s = 0.f, d = 0.f;
    for (int c = lane; c < C; c += 32) {
        float v = hp[c];
        s += v * att_s[hh * C + c];
        d += v * att_d[hh * C + c];
    }
#pragma unroll
    for (int o = 16; o; o >>= 1) {
        s += __shfl_xor_sync(0xffffffffu, s, o);
        d += __shfl_xor_sync(0xffffffffu, d, o);
    }
    if (lane == 0) { asrc[w] = s; adst[w] = d; }
}

__global__ void init_neg_inf(float* __restrict__ p, int n) {
    int i = blockIdx.x * blockDim.x + threadIdx.x;
    if (i < n) p[i] = -INFINITY;
}

// ---------------- edge pass 1: e = leaky_relu, segment max -------------------
template <int H>
__global__ void edge_max_kernel(const int* __restrict__ ei, int E, int ETot,
                                const float* __restrict__ asrc,
                                const float* __restrict__ adst,
                                float* __restrict__ ev, float* __restrict__ m) {
    int e = blockIdx.x * blockDim.x + threadIdx.x;
    if (e >= ETot) return;
    int s, d; edge_sd(e, ei, E, s, d);
#pragma unroll
    for (int h = 0; h < H; h++) {
        float v = asrc[s * H + h] + adst[d * H + h];
        v = v > 0.f ? v : 0.2f * v;
        ev[(size_t)e * H + h] = v;
        atomicMaxF(&m[d * H + h], v);
    }
}

// ---------------- edge pass 2: exp + segment sum -----------------------------
template <int H>
__global__ void edge_exp_kernel(const int* __restrict__ ei, int E, int ETot,
                                float* __restrict__ ev,
                                const float* __restrict__ m,
                                float* __restrict__ den) {
    int e = blockIdx.x * blockDim.x + threadIdx.x;
    if (e >= ETot) return;
    int s, d; edge_sd(e, ei, E, s, d);
    (void)s;
#pragma unroll
    for (int h = 0; h < H; h++) {
        float ex = __expf(ev[(size_t)e * H + h] - m[d * H + h]);
        ev[(size_t)e * H + h] = ex;
        atomicAdd(&den[d * H + h], ex);
    }
}

// ---------------- edge pass 3: scatter alpha * h[src] into agg[dst] ----------
template <int H, int C>
__global__ __launch_bounds__(256)
void scatter_kernel(const int* __restrict__ ei, int E, int ETot,
                    const float* __restrict__ ev, const float* __restrict__ den,
                    const float* __restrict__ feat, float* __restrict__ out) {
    int w = (blockIdx.x * blockDim.x + threadIdx.x) >> 5;
    int lane = threadIdx.x & 31;
    if (w >= ETot) return;
    int s, d; edge_sd(w, ei, E, s, d);
    float alpha[H];
#pragma unroll
    for (int h = 0; h < H; h++)
        alpha[h] = ev[(size_t)w * H + h] / den[d * H + h];

    const float4* fs = (const float4*)(feat + (size_t)s * H * C);
    float4* fo = (float4*)(out + (size_t)d * H * C);
    constexpr int NV = H * C / 4;       // 128 (H=4) or 32 (H=1)
    constexpr int IT = NV / 32;         // 4 or 1; with C=128, head index == it
#pragma unroll
    for (int it = 0; it < IT; ++it) {
        int i = it * 32 + lane;
        float4 v = fs[i];
        float a = alpha[it];            // (i*4)/C == it for C==128
        v.x *= a; v.y *= a; v.z *= a; v.w *= a;
        redAdd4(&fo[i], v);
    }
}

// ---------------- bias (+optional relu) --------------------------------------
__global__ void bias_act_kernel(const float* __restrict__ in,
                                const float* __restrict__ b,
                                float* __restrict__ out,
                                int total, int F, int doRelu) {
    int i = blockIdx.x * blockDim.x + threadIdx.x;
    if (i >= total) return;
    float v = in[i] + b[i % F];
    if (doRelu) v = fmaxf(v, 0.f);
    out[i] = v;
}

// ---------------- host driver ------------------------------------------------
static void gat_layer(const float* xin, int K, const float* W,
                      const float* att_s, const float* att_d, const float* bias,
                      int H, int C, bool relu,
                      const int* ei, int E, int ETot,
                      float* hfeat, float* agg,
                      float* asrc, float* adst, float* m, float* den, float* ev,
                      float* out) {
    int N = N_NODES;
    int F = H * C;

    // GEMM: hfeat = xin @ W   [N, F]
    dim3 gg(F / 128, (N + 127) / 128);
    gemm_kernel<<<gg, 256>>>(xin, W, hfeat, N, K, F);

    // attention scores
    int warps = N * H;
    attn_kernel<<<(warps * 32 + 255) / 256, 256>>>(hfeat, att_s, att_d, asrc, adst, N, H, C);

    // init m=-inf, den=0, agg=0
    init_neg_inf<<<(N * H + 255) / 256, 256>>>(m, N * H);
    cudaMemsetAsync(den, 0, (size_t)N * H * sizeof(float));
    cudaMemsetAsync(agg, 0, (size_t)N * F * sizeof(float));

    int eb = (ETot + 255) / 256;
    long long sthreads = (long long)ETot * 32;
    int sb = (int)((sthreads + 255) / 256);
    if (H == 4) {
        edge_max_kernel<4><<<eb, 256>>>(ei, E, ETot, asrc, adst, ev, m);
        edge_exp_kernel<4><<<eb, 256>>>(ei, E, ETot, ev, m, den);
        scatter_kernel<4, 128><<<sb, 256>>>(ei, E, ETot, ev, den, hfeat, agg);
    } else {
        edge_max_kernel<1><<<eb, 256>>>(ei, E, ETot, asrc, adst, ev, m);
        edge_exp_kernel<1><<<eb, 256>>>(ei, E, ETot, ev, m, den);
        scatter_kernel<1, 128><<<sb, 256>>>(ei, E, ETot, ev, den, hfeat, agg);
    }

    // bias + activation
    int total = N * F;
    bias_act_kernel<<<(total + 255) / 256, 256>>>(agg, bias, out, total, F, relu ? 1 : 0);
}

extern "C" void kernel_launch(void* const* d_in, const int* in_sizes, int n_in,
                              void* d_out, int out_size) {
    const float* x   = (const float*)d_in[0];
    const int*   ei  = (const int*)d_in[1];   // int32 (JAX x64 disabled)
    const float* W1  = (const float*)d_in[2];
    const float* as1 = (const float*)d_in[3];
    const float* ad1 = (const float*)d_in[4];
    const float* b1  = (const float*)d_in[5];
    const float* W2  = (const float*)d_in[6];
    const float* as2 = (const float*)d_in[7];
    const float* ad2 = (const float*)d_in[8];
    const float* b2  = (const float*)d_in[9];
    const float* W3  = (const float*)d_in[10];
    const float* as3 = (const float*)d_in[11];
    const float* ad3 = (const float*)d_in[12];
    const float* b3  = (const float*)d_in[13];

    int E = in_sizes[1] / 2;
    int ETot = E + N_NODES;

    float *hA, *hB, *agg, *asrc, *adst, *m, *den, *ev;
    cudaGetSymbolAddress((void**)&hA,   g_hA);
    cudaGetSymbolAddress((void**)&hB,   g_hB);
    cudaGetSymbolAddress((void**)&agg,  g_agg);
    cudaGetSymbolAddress((void**)&asrc, g_asrc);
    cudaGetSymbolAddress((void**)&adst, g_adst);
    cudaGetSymbolAddress((void**)&m,    g_m);
    cudaGetSymbolAddress((void**)&den,  g_den);
    cudaGetSymbolAddress((void**)&ev,   g_e);

    // Layer 1: 256 -> 4x128, concat + relu
    gat_layer(x, F_IN, W1, as1, ad1, b1, HEADS, CH, true,
              ei, E, ETot, hA, agg, asrc, adst, m, den, ev, hB);
    // Layer 2: 512 -> 4x128, concat + relu
    gat_layer(hB, D_HID, W2, as2, ad2, b2, HEADS, CH, true,
              ei, E, ETot, hA, agg, asrc, adst, m, den, ev, hB);
    // Layer 3: 512 -> 1x128, mean over 1 head == identity, +bias, no relu
    gat_layer(hB, D_HID, W3, as3, ad3, b3, 1, D_OUT, false,
              ei, E, ETot, hA, agg, asrc, adst, m, den, ev, (float*)d_out);
}

// round 3
// speedup vs baseline: 1.8474x; 1.8474x over previous
#include <cuda_runtime.h>
#include <math.h>
#include <stdint.h>

#define N_NODES 30000
#define F_IN    256
#define HEADS   4
#define CH      128
#define D_HID   (HEADS * CH)   // 512
#define D_OUT   128
#define E_MAX   480000
#define ET_MAX  (E_MAX + N_NODES)  // 510000

// ---------------- scratch (device globals; no allocations allowed) ----------
__device__ float g_hA[(size_t)N_NODES * D_HID];
__device__ float g_hB[(size_t)N_NODES * D_HID];
__device__ float g_agg[(size_t)N_NODES * D_HID];
__device__ float g_asrc[N_NODES * HEADS];
__device__ float g_adst[N_NODES * HEADS];
__device__ float g_m[N_NODES * HEADS];
__device__ float g_den[N_NODES * HEADS];
__device__ float g_e[(size_t)ET_MAX * HEADS];

// ---------------- helpers ---------------------------------------------------
__device__ __forceinline__ void atomicMaxF(float* addr, float val) {
    int* ai = (int*)addr;
    int old = *ai;
    while (__int_as_float(old) < val) {
        int assumed = old;
        old = atomicCAS(ai, assumed, __float_as_int(val));
        if (old == assumed) break;
    }
}

__device__ __forceinline__ void redAdd4(float4* ptr, float4 v) {
    asm volatile("red.global.add.v4.f32 [%0], {%1,%2,%3,%4};"
                 :: "l"(ptr), "f"(v.x), "f"(v.y), "f"(v.z), "f"(v.w)
                 : "memory");
}

__device__ __forceinline__ void edge_sd(int e, const int* __restrict__ ei,
                                        int E, int& s, int& d) {
    if (e < E) { s = ei[e]; d = ei[E + e]; }
    else       { s = d = e - E; }
}

__device__ __forceinline__ uint32_t f2tf(float f) {
    uint32_t u;
    asm("cvt.rna.tf32.f32 %0, %1;" : "=r"(u) : "f"(f));
    return u;
}

__device__ __forceinline__ void mma_tf32(float* c, const uint32_t* a, const uint32_t* b) {
    asm volatile(
        "mma.sync.aligned.m16n8k8.row.col.f32.tf32.tf32.f32 "
        "{%0,%1,%2,%3}, {%4,%5,%6,%7}, {%8,%9}, {%0,%1,%2,%3};"
        : "+f"(c[0]), "+f"(c[1]), "+f"(c[2]), "+f"(c[3])
        : "r"(a[0]), "r"(a[1]), "r"(a[2]), "r"(a[3]), "r"(b[0]), "r"(b[1]));
}

// ---------------- tf32 tensor-core GEMM: C[M,N] = A[M,K] @ B[K,N] ------------
// 128x128x32 block tile, 8 warps (4 M x 2 N), warp tile 32x64, m16n8k8 mma.
// Requires K % 32 == 0, N % 128 == 0. M guarded.
__global__ __launch_bounds__(256, 2)
void gemm_tf32_kernel(const float* __restrict__ A, const float* __restrict__ B,
                      float* __restrict__ C, int M, int K, int N) {
    constexpr int BM = 128, BN = 128, BK = 32;
    constexpr int AP = BK + 4;   // 36 floats: frag banks = (4r + c) mod 32, conflict-free
    constexpr int BP = BN + 8;   // 136 floats: frag banks = (8k + g) mod 32, conflict-free
    __shared__ float As[BM * AP];   // 18432 B
    __shared__ float Bs[BK * BP];   // 17408 B

    int tid  = threadIdx.x;
    int lane = tid & 31;
    int warp = tid >> 5;
    int warpM = warp & 3;     // 0..3 -> 32-row slab
    int warpN = warp >> 2;    // 0..1 -> 64-col slab
    int bm = blockIdx.y * BM;
    int bn = blockIdx.x * BN;

    float acc[2][8][4];
#pragma unroll
    for (int mt = 0; mt < 2; mt++)
#pragma unroll
        for (int nt = 0; nt < 8; nt++)
#pragma unroll
            for (int i = 0; i < 4; i++) acc[mt][nt][i] = 0.f;

    for (int k0 = 0; k0 < K; k0 += BK) {
        // load A tile: 128 x 32 floats = 1024 float4
#pragma unroll
        for (int i = 0; i < 4; i++) {
            int lin = tid + i * 256;
            int r = lin >> 3, q = lin & 7;
            float4 v = make_float4(0.f, 0.f, 0.f, 0.f);
            if (bm + r < M)
                v = *(const float4*)&A[(size_t)(bm + r) * K + k0 + q * 4];
            *(float4*)&As[r * AP + q * 4] = v;
        }
        // load B tile: 32 x 128 floats = 1024 float4
#pragma unroll
        for (int i = 0; i < 4; i++) {
            int lin = tid + i * 256;
            int r = lin >> 5, q = lin & 31;
            float4 v = *(const float4*)&B[(size_t)(k0 + r) * N + bn + q * 4];
            *(float4*)&Bs[r * BP + q * 4] = v;
        }
        __syncthreads();

#pragma unroll
        for (int kk = 0; kk < BK / 8; kk++) {
            int kb = kk * 8;
            uint32_t af[2][4], bf[8][2];
            int ar = warpM * 32 + (lane >> 2);
            int ac = kb + (lane & 3);
#pragma unroll
            for (int mt = 0; mt < 2; mt++) {
                int r = ar + mt * 16;
                af[mt][0] = f2tf(As[r * AP + ac]);
                af[mt][1] = f2tf(As[(r + 8) * AP + ac]);
                af[mt][2] = f2tf(As[r * AP + ac + 4]);
                af[mt][3] = f2tf(As[(r + 8) * AP + ac + 4]);
            }
            int br = kb + (lane & 3);
            int bc = warpN * 64 + (lane >> 2);
#pragma unroll
            for (int nt = 0; nt < 8; nt++) {
                bf[nt][0] = f2tf(Bs[br * BP + bc + nt * 8]);
                bf[nt][1] = f2tf(Bs[(br + 4) * BP + bc + nt * 8]);
            }
#pragma unroll
            for (int mt = 0; mt < 2; mt++)
#pragma unroll
                for (int nt = 0; nt < 8; nt++)
                    mma_tf32(acc[mt][nt], af[mt], bf[nt]);
        }
        __syncthreads();
    }

    // store
#pragma unroll
    for (int mt = 0; mt < 2; mt++) {
        int r0 = bm + warpM * 32 + mt * 16 + (lane >> 2);
#pragma unroll
        for (int nt = 0; nt < 8; nt++) {
            int c0 = bn + warpN * 64 + nt * 8 + (lane & 3) * 2;
            if (r0 < M)
                *(float2*)&C[(size_t)r0 * N + c0] =
                    make_float2(acc[mt][nt][0], acc[mt][nt][1]);
            if (r0 + 8 < M)
                *(float2*)&C[(size_t)(r0 + 8) * N + c0] =
                    make_float2(acc[mt][nt][2], acc[mt][nt][3]);
        }
    }
}

// ---------------- attention scores ------------------------------------------
__global__ void attn_kernel(const float* __restrict__ h,
                            const float* __restrict__ att_s,
                            const float* __restrict__ att_d,
                            float* __restrict__ asrc, float* __restrict__ adst,
                            int N, int H, int C) {
    int w = (blockIdx.x * blockDim.x + threadIdx.x) >> 5;
    int lane = threadIdx.x & 31;
    if (w >= N * H) return;
    int n = w / H, hh = w - n * H;
    const float* hp = h + ((size_t)n * H + hh) * C;
    float s = 0.f, d = 0.f;
    for (int c = lane; c < C; c += 32) {
        float v = hp[c];
        s += v * att_s[hh * C + c];
        d += v * att_d[hh * C + c];
    }
#pragma unroll
    for (int o = 16; o; o >>= 1) {
        s += __shfl_xor_sync(0xffffffffu, s, o);
        d += __shfl_xor_sync(0xffffffffu, d, o);
    }
    if (lane == 0) { asrc[w] = s; adst[w] = d; }
}

__global__ void init_neg_inf(float* __restrict__ p, int n) {
    int i = blockIdx.x * blockDim.x + threadIdx.x;
    if (i < n) p[i] = -INFINITY;
}

// ---------------- edge pass 1: leaky_relu + segment max ----------------------
template <int H>
__global__ void edge_max_kernel(const int* __restrict__ ei, int E, int ETot,
                                const float* __restrict__ asrc,
                                const float* __restrict__ adst,
                                float* __restrict__ ev, float* __restrict__ m) {
    int e = blockIdx.x * blockDim.x + threadIdx.x;
    if (e >= ETot) return;
    int s, d; edge_sd(e, ei, E, s, d);
#pragma unroll
    for (int h = 0; h < H; h++) {
        float v = asrc[s * H + h] + adst[d * H + h];
        v = v > 0.f ? v : 0.2f * v;
        ev[(size_t)e * H + h] = v;
        atomicMaxF(&m[d * H + h], v);
    }
}

// ---------------- edge pass 2: exp + segment sum -----------------------------
template <int H>
__global__ void edge_exp_kernel(const int* __restrict__ ei, int E, int ETot,
                                float* __restrict__ ev,
                                const float* __restrict__ m,
                                float* __restrict__ den) {
    int e = blockIdx.x * blockDim.x + threadIdx.x;
    if (e >= ETot) return;
    int s, d; edge_sd(e, ei, E, s, d);
    (void)s;
#pragma unroll
    for (int h = 0; h < H; h++) {
        float ex = __expf(ev[(size_t)e * H + h] - m[d * H + h]);
        ev[(size_t)e * H + h] = ex;
        atomicAdd(&den[d * H + h], ex);
    }
}

// ---------------- edge pass 3: scatter alpha * h[src] into agg[dst] ----------
template <int H, int C>
__global__ __launch_bounds__(256)
void scatter_kernel(const int* __restrict__ ei, int E, int ETot,
                    const float* __restrict__ ev, const float* __restrict__ den,
                    const float* __restrict__ feat, float* __restrict__ out) {
    int w = (blockIdx.x * blockDim.x + threadIdx.x) >> 5;
    int lane = threadIdx.x & 31;
    if (w >= ETot) return;
    int s, d; edge_sd(w, ei, E, s, d);
    float alpha[H];
#pragma unroll
    for (int h = 0; h < H; h++)
        alpha[h] = ev[(size_t)w * H + h] / den[d * H + h];

    const float4* fs = (const float4*)(feat + (size_t)s * H * C);
    float4* fo = (float4*)(out + (size_t)d * H * C);
    constexpr int NV = H * C / 4;
    constexpr int IT = NV / 32;
#pragma unroll
    for (int it = 0; it < IT; ++it) {
        int i = it * 32 + lane;
        float4 v = fs[i];
        float a = alpha[it];
        v.x *= a; v.y *= a; v.z *= a; v.w *= a;
        redAdd4(&fo[i], v);
    }
}

// ---------------- bias (+optional relu) --------------------------------------
__global__ void bias_act_kernel(const float* __restrict__ in,
                                const float* __restrict__ b,
                                float* __restrict__ out,
                                int total, int F, int doRelu) {
    int i = blockIdx.x * blockDim.x + threadIdx.x;
    if (i >= total) return;
    float v = in[i] + b[i % F];
    if (doRelu) v = fmaxf(v, 0.f);
    out[i] = v;
}

// ---------------- host driver ------------------------------------------------
static void gat_layer(const float* xin, int K, const float* W,
                      const float* att_s, const float* att_d, const float* bias,
                      int H, int C, bool relu,
                      const int* ei, int E, int ETot,
                      float* hfeat, float* agg,
                      float* asrc, float* adst, float* m, float* den, float* ev,
                      float* out) {
    int N = N_NODES;
    int F = H * C;

    dim3 gg(F / 128, (N + 127) / 128);
    gemm_tf32_kernel<<<gg, 256>>>(xin, W, hfeat, N, K, F);

    int warps = N * H;
    attn_kernel<<<(warps * 32 + 255) / 256, 256>>>(hfeat, att_s, att_d, asrc, adst, N, H, C);

    init_neg_inf<<<(N * H + 255) / 256, 256>>>(m, N * H);
    cudaMemsetAsync(den, 0, (size_t)N * H * sizeof(float));
    cudaMemsetAsync(agg, 0, (size_t)N * F * sizeof(float));

    int eb = (ETot + 255) / 256;
    long long sthreads = (long long)ETot * 32;
    int sb = (int)((sthreads + 255) / 256);
    if (H == 4) {
        edge_max_kernel<4><<<eb, 256>>>(ei, E, ETot, asrc, adst, ev, m);
        edge_exp_kernel<4><<<eb, 256>>>(ei, E, ETot, ev, m, den);
        scatter_kernel<4, 128><<<sb, 256>>>(ei, E, ETot, ev, den, hfeat, agg);
    } else {
        edge_max_kernel<1><<<eb, 256>>>(ei, E, ETot, asrc, adst, ev, m);
        edge_exp_kernel<1><<<eb, 256>>>(ei, E, ETot, ev, m, den);
        scatter_kernel<1, 128><<<sb, 256>>>(ei, E, ETot, ev, den, hfeat, agg);
    }

    int total = N * F;
    bias_act_kernel<<<(total + 255) / 256, 256>>>(agg, bias, out, total, F, relu ? 1 : 0);
}

extern "C" void kernel_launch(void* const* d_in, const int* in_sizes, int n_in,
                              void* d_out, int out_size) {
    const float* x   = (const float*)d_in[0];
    const int*   ei  = (const int*)d_in[1];   // int32 (JAX x64 disabled)
    const float* W1  = (const float*)d_in[2];
    const float* as1 = (const float*)d_in[3];
    const float* ad1 = (const float*)d_in[4];
    const float* b1  = (const float*)d_in[5];
    const float* W2  = (const float*)d_in[6];
    const float* as2 = (const float*)d_in[7];
    const float* ad2 = (const float*)d_in[8];
    const float* b2  = (const float*)d_in[9];
    const float* W3  = (const float*)d_in[10];
    const float* as3 = (const float*)d_in[11];
    const float* ad3 = (const float*)d_in[12];
    const float* b3  = (const float*)d_in[13];

    int E = in_sizes[1] / 2;
    int ETot = E + N_NODES;

    float *hA, *hB, *agg, *asrc, *adst, *m, *den, *ev;
    cudaGetSymbolAddress((void**)&hA,   g_hA);
    cudaGetSymbolAddress((void**)&hB,   g_hB);
    cudaGetSymbolAddress((void**)&agg,  g_agg);
    cudaGetSymbolAddress((void**)&asrc, g_asrc);
    cudaGetSymbolAddress((void**)&adst, g_adst);
    cudaGetSymbolAddress((void**)&m,    g_m);
    cudaGetSymbolAddress((void**)&den,  g_den);
    cudaGetSymbolAddress((void**)&ev,   g_e);

    gat_layer(x, F_IN, W1, as1, ad1, b1, HEADS, CH, true,
              ei, E, ETot, hA, agg, asrc, adst, m, den, ev, hB);
    gat_layer(hB, D_HID, W2, as2, ad2, b2, HEADS, CH, true,
              ei, E, ETot, hA, agg, asrc, adst, m, den, ev, hB);
    gat_layer(hB, D_HID, W3, as3, ad3, b3, 1, D_OUT, false,
              ei, E, ETot, hA, agg, asrc, adst, m, den, ev, (float*)d_out);
}

// round 5
// speedup vs baseline: 3.3101x; 1.7918x over previous
#include <cuda_runtime.h>
#include <math.h>
#include <stdint.h>

#define N_NODES 30000
#define F_IN    256
#define HEADS   4
#define CH      128
#define D_HID   (HEADS * CH)   // 512
#define D_OUT   128
#define E_MAX   480000
#define ET_MAX  (E_MAX + N_NODES)  // 510000

// ---------------- scratch (device globals; no allocations allowed) ----------
__device__ float g_hA[(size_t)N_NODES * D_HID];
__device__ float g_hB[(size_t)N_NODES * D_HID];
__device__ float g_asrc[N_NODES * HEADS];
__device__ float g_adst[N_NODES * HEADS];
__device__ int   g_deg[N_NODES];
__device__ int   g_cursor[N_NODES];
__device__ int   g_offs[N_NODES + 1];
__device__ int   g_csrc[ET_MAX];

// ---------------- helpers ---------------------------------------------------
__device__ __forceinline__ void edge_sd(int e, const int* __restrict__ ei,
                                        int E, int& s, int& d) {
    if (e < E) { s = ei[e]; d = ei[E + e]; }
    else       { s = d = e - E; }   // self-loops appended
}

__device__ __forceinline__ uint32_t f2tf(float f) {
    uint32_t u;
    asm("cvt.rna.tf32.f32 %0, %1;" : "=r"(u) : "f"(f));
    return u;
}

__device__ __forceinline__ void mma_tf32(float* c, const uint32_t* a, const uint32_t* b) {
    asm volatile(
        "mma.sync.aligned.m16n8k8.row.col.f32.tf32.tf32.f32 "
        "{%0,%1,%2,%3}, {%4,%5,%6,%7}, {%8,%9}, {%0,%1,%2,%3};"
        : "+f"(c[0]), "+f"(c[1]), "+f"(c[2]), "+f"(c[3])
        : "r"(a[0]), "r"(a[1]), "r"(a[2]), "r"(a[3]), "r"(b[0]), "r"(b[1]));
}

// ---------------- tf32 tensor-core GEMM: C[M,N] = A[M,K] @ B[K,N] ------------
__global__ __launch_bounds__(256, 2)
void gemm_tf32_kernel(const float* __restrict__ A, const float* __restrict__ B,
                      float* __restrict__ C, int M, int K, int N) {
    constexpr int BM = 128, BN = 128, BK = 32;
    constexpr int AP = BK + 4;
    constexpr int BP = BN + 8;
    __shared__ float As[BM * AP];
    __shared__ float Bs[BK * BP];

    int tid  = threadIdx.x;
    int lane = tid & 31;
    int warp = tid >> 5;
    int warpM = warp & 3;
    int warpN = warp >> 2;
    int bm = blockIdx.y * BM;
    int bn = blockIdx.x * BN;

    float acc[2][8][4];
#pragma unroll
    for (int mt = 0; mt < 2; mt++)
#pragma unroll
        for (int nt = 0; nt < 8; nt++)
#pragma unroll
            for (int i = 0; i < 4; i++) acc[mt][nt][i] = 0.f;

    for (int k0 = 0; k0 < K; k0 += BK) {
#pragma unroll
        for (int i = 0; i < 4; i++) {
            int lin = tid + i * 256;
            int r = lin >> 3, q = lin & 7;
            float4 v = make_float4(0.f, 0.f, 0.f, 0.f);
            if (bm + r < M)
                v = *(const float4*)&A[(size_t)(bm + r) * K + k0 + q * 4];
            *(float4*)&As[r * AP + q * 4] = v;
        }
#pragma unroll
        for (int i = 0; i < 4; i++) {
            int lin = tid + i * 256;
            int r = lin >> 5, q = lin & 31;
            float4 v = *(const float4*)&B[(size_t)(k0 + r) * N + bn + q * 4];
            *(float4*)&Bs[r * BP + q * 4] = v;
        }
        __syncthreads();

#pragma unroll
        for (int kk = 0; kk < BK / 8; kk++) {
            int kb = kk * 8;
            uint32_t af[2][4], bf[8][2];
            int ar = warpM * 32 + (lane >> 2);
            int ac = kb + (lane & 3);
#pragma unroll
            for (int mt = 0; mt < 2; mt++) {
                int r = ar + mt * 16;
                af[mt][0] = f2tf(As[r * AP + ac]);
                af[mt][1] = f2tf(As[(r + 8) * AP + ac]);
                af[mt][2] = f2tf(As[r * AP + ac + 4]);
                af[mt][3] = f2tf(As[(r + 8) * AP + ac + 4]);
            }
            int br = kb + (lane & 3);
            int bc = warpN * 64 + (lane >> 2);
#pragma unroll
            for (int nt = 0; nt < 8; nt++) {
                bf[nt][0] = f2tf(Bs[br * BP + bc + nt * 8]);
                bf[nt][1] = f2tf(Bs[(br + 4) * BP + bc + nt * 8]);
            }
#pragma unroll
            for (int mt = 0; mt < 2; mt++)
#pragma unroll
                for (int nt = 0; nt < 8; nt++)
                    mma_tf32(acc[mt][nt], af[mt], bf[nt]);
        }
        __syncthreads();
    }

#pragma unroll
    for (int mt = 0; mt < 2; mt++) {
        int r0 = bm + warpM * 32 + mt * 16 + (lane >> 2);
#pragma unroll
        for (int nt = 0; nt < 8; nt++) {
            int c0 = bn + warpN * 64 + nt * 8 + (lane & 3) * 2;
            if (r0 < M)
                *(float2*)&C[(size_t)r0 * N + c0] =
                    make_float2(acc[mt][nt][0], acc[mt][nt][1]);
            if (r0 + 8 < M)
                *(float2*)&C[(size_t)(r0 + 8) * N + c0] =
                    make_float2(acc[mt][nt][2], acc[mt][nt][3]);
        }
    }
}

// ---------------- attention scores ------------------------------------------
__global__ void attn_kernel(const float* __restrict__ h,
                            const float* __restrict__ att_s,
                            const float* __restrict__ att_d,
                            float* __restrict__ asrc, float* __restrict__ adst,
                            int N, int H, int C) {
    int w = (blockIdx.x * blockDim.x + threadIdx.x) >> 5;
    int lane = threadIdx.x & 31;
    if (w >= N * H) return;
    int n = w / H, hh = w - n * H;
    const float* hp = h + ((size_t)n * H + hh) * C;
    float s = 0.f, d = 0.f;
    for (int c = lane; c < C; c += 32) {
        float v = hp[c];
        s += v * att_s[hh * C + c];
        d += v * att_d[hh * C + c];
    }
#pragma unroll
    for (int o = 16; o; o >>= 1) {
        s += __shfl_xor_sync(0xffffffffu, s, o);
        d += __shfl_xor_sync(0xffffffffu, d, o);
    }
    if (lane == 0) { asrc[w] = s; adst[w] = d; }
}

// ---------------- CSR build --------------------------------------------------
__global__ void deg_kernel(const int* __restrict__ ei, int E, int ETot,
                           int* __restrict__ deg) {
    int e = blockIdx.x * blockDim.x + threadIdx.x;
    if (e >= ETot) return;
    int s, d; edge_sd(e, ei, E, s, d);
    (void)s;
    atomicAdd(&deg[d], 1);
}

__global__ __launch_bounds__(1024)
void scan_kernel(const int* __restrict__ deg, int* __restrict__ offs, int N) {
    __shared__ int sums[1024];
    int tid = threadIdx.x;
    int chunk = (N + 1023) / 1024;
    int base = tid * chunk;
    int s = 0;
    for (int i = 0; i < chunk; i++) {
        int idx = base + i;
        if (idx < N) s += deg[idx];
    }
    sums[tid] = s;
    __syncthreads();
    for (int off = 1; off < 1024; off <<= 1) {
        int v = (tid >= off) ? sums[tid - off] : 0;
        __syncthreads();
        sums[tid] += v;
        __syncthreads();
    }
    int run = (tid == 0) ? 0 : sums[tid - 1];
    for (int i = 0; i < chunk; i++) {
        int idx = base + i;
        if (idx < N) { offs[idx] = run; run += deg[idx]; }
    }
    if (tid == 1023) offs[N] = run;
}

__global__ void fill_kernel(const int* __restrict__ ei, int E, int ETot,
                            const int* __restrict__ offs,
                            int* __restrict__ cursor, int* __restrict__ csrc) {
    int e = blockIdx.x * blockDim.x + threadIdx.x;
    if (e >= ETot) return;
    int s, d; edge_sd(e, ei, E, s, d);
    int pos = atomicAdd(&cursor[d], 1);
    csrc[offs[d] + pos] = s;
}

// ---------------- fused softmax + aggregation + bias + relu ------------------
// One warp per dst node. Pass 1: softmax denominator (lane-parallel over edges,
// no max-subtraction: scores are O(1)). Pass 2: register-accumulate alpha*h[src],
// alpha via lane-specialized exp + shfl broadcast. Epilogue: bias (+relu), one
// store per output row (no atomics).
template <int H, int C, bool RELU>
__global__ __launch_bounds__(256)
void agg_kernel(const int* __restrict__ offs, const int* __restrict__ csrc,
                const float* __restrict__ asrc, const float* __restrict__ adst,
                const float* __restrict__ feat, const float* __restrict__ bias,
                float* __restrict__ out, int N) {
    int d = (blockIdx.x * blockDim.x + threadIdx.x) >> 5;
    int lane = threadIdx.x & 31;
    if (d >= N) return;
    int beg = offs[d], end = offs[d + 1];

    float ad[H];
#pragma unroll
    for (int h = 0; h < H; h++) ad[h] = adst[d * H + h];

    // pass 1: denominator per head
    float den[H];
#pragma unroll
    for (int h = 0; h < H; h++) den[h] = 0.f;
    for (int i = beg + lane; i < end; i += 32) {
        int s = csrc[i];
#pragma unroll
        for (int h = 0; h < H; h++) {
            float v = asrc[s * H + h] + ad[h];
            v = v > 0.f ? v : 0.2f * v;
            den[h] += __expf(v);
        }
    }
#pragma unroll
    for (int o = 16; o; o >>= 1)
#pragma unroll
        for (int h = 0; h < H; h++)
            den[h] += __shfl_xor_sync(0xffffffffu, den[h], o);

    float inv_den_l = 0.f, ad_l = 0.f;
    if (lane < H) {
        ad_l = adst[d * H + lane];
#pragma unroll
        for (int h = 0; h < H; h++)
            if (lane == h) inv_den_l = 1.f / den[h];
    }

    constexpr int IT = (H * C) / 128;   // 4 (H=4) or 1 (H=1); chunk it == head it
    float4 acc[IT];
#pragma unroll
    for (int it = 0; it < IT; it++) acc[it] = make_float4(0.f, 0.f, 0.f, 0.f);

    for (int i = beg; i < end; ++i) {
        int s = csrc[i];
        float av = 0.f;
        if (lane < H) {
            float v = asrc[s * H + lane] + ad_l;
            v = v > 0.f ? v : 0.2f * v;
            av = __expf(v) * inv_den_l;
        }
        const float4* fs = (const float4*)(feat + (size_t)s * (H * C));
#pragma unroll
        for (int it = 0; it < IT; it++) {
            float a = __shfl_sync(0xffffffffu, av, it);
            float4 v = fs[it * 32 + lane];
            acc[it].x += a * v.x;
            acc[it].y += a * v.y;
            acc[it].z += a * v.z;
            acc[it].w += a * v.w;
        }
    }

    float4* po = (float4*)(out + (size_t)d * (H * C));
    const float4* pb = (const float4*)bias;
#pragma unroll
    for (int it = 0; it < IT; it++) {
        float4 b = pb[it * 32 + lane];
        float4 v = acc[it];
        v.x += b.x; v.y += b.y; v.z += b.z; v.w += b.w;
        if (RELU) {
            v.x = fmaxf(v.x, 0.f); v.y = fmaxf(v.y, 0.f);
            v.z = fmaxf(v.z, 0.f); v.w = fmaxf(v.w, 0.f);
        }
        po[it * 32 + lane] = v;
    }
}

// ---------------- host driver ------------------------------------------------
template <int H, int C, bool RELU>
static void gat_layer(const float* xin, int K, const float* W,
                      const float* att_s, const float* att_d, const float* bias,
                      const int* offs, const int* csrc,
                      float* hfeat, float* asrc, float* adst, float* out) {
    int N = N_NODES;
    int F = H * C;

    dim3 gg(F / 128, (N + 127) / 128);
    gemm_tf32_kernel<<<gg, 256>>>(xin, W, hfeat, N, K, F);

    int warps = N * H;
    attn_kernel<<<(warps * 32 + 255) / 256, 256>>>(hfeat, att_s, att_d, asrc, adst, N, H, C);

    long long t = (long long)N * 32;
    agg_kernel<H, C, RELU><<<(int)((t + 255) / 256), 256>>>(
        offs, csrc, asrc, adst, hfeat, bias, out, N);
}

extern "C" void kernel_launch(void* const* d_in, const int* in_sizes, int n_in,
                              void* d_out, int out_size) {
    const float* x   = (const float*)d_in[0];
    const int*   ei  = (const int*)d_in[1];   // int32 (JAX x64 disabled)
    const float* W1  = (const float*)d_in[2];
    const float* as1 = (const float*)d_in[3];
    const float* ad1 = (const float*)d_in[4];
    const float* b1  = (const float*)d_in[5];
    const float* W2  = (const float*)d_in[6];
    const float* as2 = (const float*)d_in[7];
    const float* ad2 = (const float*)d_in[8];
    const float* b2  = (const float*)d_in[9];
    const float* W3  = (const float*)d_in[10];
    const float* as3 = (const float*)d_in[11];
    const float* ad3 = (const float*)d_in[12];
    const float* b3  = (const float*)d_in[13];

    int E = in_sizes[1] / 2;
    int ETot = E + N_NODES;

    float *hA, *hB, *asrc, *adst;
    int *deg, *cursor, *offs, *csrc;
    cudaGetSymbolAddress((void**)&hA,     g_hA);
    cudaGetSymbolAddress((void**)&hB,     g_hB);
    cudaGetSymbolAddress((void**)&asrc,   g_asrc);
    cudaGetSymbolAddress((void**)&adst,   g_adst);
    cudaGetSymbolAddress((void**)&deg,    g_deg);
    cudaGetSymbolAddress((void**)&cursor, g_cursor);
    cudaGetSymbolAddress((void**)&offs,   g_offs);
    cudaGetSymbolAddress((void**)&csrc,   g_csrc);

    // ---- build CSR (dst-indexed) once ----
    cudaMemsetAsync(deg, 0, N_NODES * sizeof(int));
    cudaMemsetAsync(cursor, 0, N_NODES * sizeof(int));
    int eb = (ETot + 255) / 256;
    deg_kernel<<<eb, 256>>>(ei, E, ETot, deg);
    scan_kernel<<<1, 1024>>>(deg, offs, N_NODES);
    fill_kernel<<<eb, 256>>>(ei, E, ETot, offs, cursor, csrc);

    // ---- 3 GAT layers ----
    gat_layer<HEADS, CH, true>(x,  F_IN,  W1, as1, ad1, b1, offs, csrc, hA, asrc, adst, hB);
    gat_layer<HEADS, CH, true>(hB, D_HID, W2, as2, ad2, b2, offs, csrc, hA, asrc, adst, hB);
    gat_layer<1, D_OUT, false>(hB, D_HID, W3, as3, ad3, b3, offs, csrc, hA, asrc, adst, (float*)d_out);
}

// round 6
// speedup vs baseline: 3.5747x; 1.0799x over previous
#include <cuda_runtime.h>
#include <math.h>
#include <stdint.h>

#define N_NODES 30000
#define F_IN    256
#define HEADS   4
#define CH      128
#define D_HID   (HEADS * CH)   // 512
#define D_OUT   128
#define E_MAX   480000
#define ET_MAX  (E_MAX + N_NODES)  // 510000

// ---------------- scratch (device globals; no allocations allowed) ----------
__device__ float g_hA[(size_t)N_NODES * D_HID];
__device__ float g_hB[(size_t)N_NODES * D_HID];
__device__ float g_asrc[N_NODES * HEADS];
__device__ float g_adst[N_NODES * HEADS];
__device__ int   g_deg[N_NODES];
__device__ int   g_cursor[N_NODES];
__device__ int   g_offs[N_NODES + 1];
__device__ int   g_csrc[ET_MAX];

// ---------------- helpers ---------------------------------------------------
__device__ __forceinline__ void edge_sd(int e, const int* __restrict__ ei,
                                        int E, int& s, int& d) {
    if (e < E) { s = ei[e]; d = ei[E + e]; }
    else       { s = d = e - E; }   // self-loops appended
}

__device__ __forceinline__ uint32_t f2tf(float f) {
    uint32_t u;
    asm("cvt.rna.tf32.f32 %0, %1;" : "=r"(u) : "f"(f));
    return u;
}

__device__ __forceinline__ void mma_tf32(float* c, const uint32_t* a, const uint32_t* b) {
    asm volatile(
        "mma.sync.aligned.m16n8k8.row.col.f32.tf32.tf32.f32 "
        "{%0,%1,%2,%3}, {%4,%5,%6,%7}, {%8,%9}, {%0,%1,%2,%3};"
        : "+f"(c[0]), "+f"(c[1]), "+f"(c[2]), "+f"(c[3])
        : "r"(a[0]), "r"(a[1]), "r"(a[2]), "r"(a[3]), "r"(b[0]), "r"(b[1]));
}

// ---------------- tf32 tensor-core GEMM with fused attention epilogue --------
// C[M,N] = A[M,K] @ B[K,N]. BN == 128 == head width, so blockIdx.x == head.
// Epilogue computes asrc/adst[n, head] = <C_row_head, att_{s,d}[head]> from the
// register-resident accumulators (no extra pass over C).
__global__ __launch_bounds__(256, 2)
void gemm_tf32_attn_kernel(const float* __restrict__ A, const float* __restrict__ B,
                           float* __restrict__ C, int M, int K, int N,
                           const float* __restrict__ att_s,
                           const float* __restrict__ att_d,
                           float* __restrict__ asrc, float* __restrict__ adst,
                           int H) {
    constexpr int BM = 128, BN = 128, BK = 32;
    constexpr int AP = BK + 4;   // conflict-free for A fragment pattern
    constexpr int BP = BN + 8;   // conflict-free for B fragment pattern
    __shared__ uint32_t As[BM * AP];   // tf32 bits
    __shared__ uint32_t Bs[BK * BP];   // tf32 bits
    __shared__ float s_as[BM];
    __shared__ float s_ad[BM];

    int tid  = threadIdx.x;
    int lane = tid & 31;
    int warp = tid >> 5;
    int warpM = warp & 3;
    int warpN = warp >> 2;
    int bm = blockIdx.y * BM;
    int bn = blockIdx.x * BN;
    int head = blockIdx.x;           // BN == C == 128

    float acc[2][8][4];
#pragma unroll
    for (int mt = 0; mt < 2; mt++)
#pragma unroll
        for (int nt = 0; nt < 8; nt++)
#pragma unroll
            for (int i = 0; i < 4; i++) acc[mt][nt][i] = 0.f;

    for (int k0 = 0; k0 < K; k0 += BK) {
        // A tile: 128 x 32, convert to tf32 on store
#pragma unroll
        for (int i = 0; i < 4; i++) {
            int lin = tid + i * 256;
            int r = lin >> 3, q = lin & 7;
            float4 v = make_float4(0.f, 0.f, 0.f, 0.f);
            if (bm + r < M)
                v = *(const float4*)&A[(size_t)(bm + r) * K + k0 + q * 4];
            uint4 u = make_uint4(f2tf(v.x), f2tf(v.y), f2tf(v.z), f2tf(v.w));
            *(uint4*)&As[r * AP + q * 4] = u;
        }
        // B tile: 32 x 128
#pragma unroll
        for (int i = 0; i < 4; i++) {
            int lin = tid + i * 256;
            int r = lin >> 5, q = lin & 31;
            float4 v = *(const float4*)&B[(size_t)(k0 + r) * N + bn + q * 4];
            uint4 u = make_uint4(f2tf(v.x), f2tf(v.y), f2tf(v.z), f2tf(v.w));
            *(uint4*)&Bs[r * BP + q * 4] = u;
        }
        __syncthreads();

#pragma unroll
        for (int kk = 0; kk < BK / 8; kk++) {
            int kb = kk * 8;
            uint32_t af[2][4], bf[8][2];
            int ar = warpM * 32 + (lane >> 2);
            int ac = kb + (lane & 3);
#pragma unroll
            for (int mt = 0; mt < 2; mt++) {
                int r = ar + mt * 16;
                af[mt][0] = As[r * AP + ac];
                af[mt][1] = As[(r + 8) * AP + ac];
                af[mt][2] = As[r * AP + ac + 4];
                af[mt][3] = As[(r + 8) * AP + ac + 4];
            }
            int br = kb + (lane & 3);
            int bc = warpN * 64 + (lane >> 2);
#pragma unroll
            for (int nt = 0; nt < 8; nt++) {
                bf[nt][0] = Bs[br * BP + bc + nt * 8];
                bf[nt][1] = Bs[(br + 4) * BP + bc + nt * 8];
            }
#pragma unroll
            for (int mt = 0; mt < 2; mt++)
#pragma unroll
                for (int nt = 0; nt < 8; nt++)
                    mma_tf32(acc[mt][nt], af[mt], bf[nt]);
        }
        __syncthreads();
    }

    // ---- store C ----
#pragma unroll
    for (int mt = 0; mt < 2; mt++) {
        int r0 = bm + warpM * 32 + mt * 16 + (lane >> 2);
#pragma unroll
        for (int nt = 0; nt < 8; nt++) {
            int c0 = bn + warpN * 64 + nt * 8 + (lane & 3) * 2;
            if (r0 < M)
                *(float2*)&C[(size_t)r0 * N + c0] =
                    make_float2(acc[mt][nt][0], acc[mt][nt][1]);
            if (r0 + 8 < M)
                *(float2*)&C[(size_t)(r0 + 8) * N + c0] =
                    make_float2(acc[mt][nt][2], acc[mt][nt][3]);
        }
    }

    // ---- fused attention dots ----
    if (tid < BM) { s_as[tid] = 0.f; s_ad[tid] = 0.f; }
    __syncthreads();

    float ps[2][2], pd[2][2];   // [mt][half]
#pragma unroll
    for (int mt = 0; mt < 2; mt++)
#pragma unroll
        for (int hh = 0; hh < 2; hh++) { ps[mt][hh] = 0.f; pd[mt][hh] = 0.f; }

#pragma unroll
    for (int nt = 0; nt < 8; nt++) {
        int cl = warpN * 64 + nt * 8 + (lane & 3) * 2;   // col within head
        float a0 = att_s[head * 128 + cl], a1 = att_s[head * 128 + cl + 1];
        float d0 = att_d[head * 128 + cl], d1 = att_d[head * 128 + cl + 1];
#pragma unroll
        for (int mt = 0; mt < 2; mt++) {
            ps[mt][0] += acc[mt][nt][0] * a0 + acc[mt][nt][1] * a1;
            pd[mt][0] += acc[mt][nt][0] * d0 + acc[mt][nt][1] * d1;
            ps[mt][1] += acc[mt][nt][2] * a0 + acc[mt][nt][3] * a1;
            pd[mt][1] += acc[mt][nt][2] * d0 + acc[mt][nt][3] * d1;
        }
    }
    // reduce over the 4 lanes sharing a row (lane&3)
#pragma unroll
    for (int o = 1; o <= 2; o <<= 1)
#pragma unroll
        for (int mt = 0; mt < 2; mt++)
#pragma unroll
            for (int hh = 0; hh < 2; hh++) {
                ps[mt][hh] += __shfl_xor_sync(0xffffffffu, ps[mt][hh], o);
                pd[mt][hh] += __shfl_xor_sync(0xffffffffu, pd[mt][hh], o);
            }
    if ((lane & 3) == 0) {
#pragma unroll
        for (int mt = 0; mt < 2; mt++)
#pragma unroll
            for (int hh = 0; hh < 2; hh++) {
                int r = warpM * 32 + mt * 16 + hh * 8 + (lane >> 2);
                atomicAdd(&s_as[r], ps[mt][hh]);
                atomicAdd(&s_ad[r], pd[mt][hh]);
            }
    }
    __syncthreads();
    if (tid < BM && bm + tid < M) {
        asrc[(bm + tid) * H + head] = s_as[tid];
        adst[(bm + tid) * H + head] = s_ad[tid];
    }
}

// ---------------- CSR build --------------------------------------------------
__global__ void deg_kernel(const int* __restrict__ ei, int E, int ETot,
                           int* __restrict__ deg) {
    int e = blockIdx.x * blockDim.x + threadIdx.x;
    if (e >= ETot) return;
    int s, d; edge_sd(e, ei, E, s, d);
    (void)s;
    atomicAdd(&deg[d], 1);
}

__global__ __launch_bounds__(1024)
void scan_kernel(const int* __restrict__ deg, int* __restrict__ offs, int N) {
    __shared__ int sums[1024];
    int tid = threadIdx.x;
    int chunk = (N + 1023) / 1024;
    int base = tid * chunk;
    int s = 0;
    for (int i = 0; i < chunk; i++) {
        int idx = base + i;
        if (idx < N) s += deg[idx];
    }
    sums[tid] = s;
    __syncthreads();
    for (int off = 1; off < 1024; off <<= 1) {
        int v = (tid >= off) ? sums[tid - off] : 0;
        __syncthreads();
        sums[tid] += v;
        __syncthreads();
    }
    int run = (tid == 0) ? 0 : sums[tid - 1];
    for (int i = 0; i < chunk; i++) {
        int idx = base + i;
        if (idx < N) { offs[idx] = run; run += deg[idx]; }
    }
    if (tid == 1023) offs[N] = run;
}

__global__ void fill_kernel(const int* __restrict__ ei, int E, int ETot,
                            const int* __restrict__ offs,
                            int* __restrict__ cursor, int* __restrict__ csrc) {
    int e = blockIdx.x * blockDim.x + threadIdx.x;
    if (e >= ETot) return;
    int s, d; edge_sd(e, ei, E, s, d);
    int pos = atomicAdd(&cursor[d], 1);
    csrc[offs[d] + pos] = s;
}

// ---------------- fused softmax + aggregation + bias + relu ------------------
template <int H, int C, bool RELU>
__global__ __launch_bounds__(256)
void agg_kernel(const int* __restrict__ offs, const int* __restrict__ csrc,
                const float* __restrict__ asrc, const float* __restrict__ adst,
                const float* __restrict__ feat, const float* __restrict__ bias,
                float* __restrict__ out, int N) {
    int d = (blockIdx.x * blockDim.x + threadIdx.x) >> 5;
    int lane = threadIdx.x & 31;
    if (d >= N) return;
    int beg = offs[d], end = offs[d + 1];

    float ad[H];
#pragma unroll
    for (int h = 0; h < H; h++) ad[h] = adst[d * H + h];

    // pass 1: softmax denominator per head (scores O(1): no max needed)
    float den[H];
#pragma unroll
    for (int h = 0; h < H; h++) den[h] = 0.f;
    for (int i = beg + lane; i < end; i += 32) {
        int s = csrc[i];
#pragma unroll
        for (int h = 0; h < H; h++) {
            float v = asrc[s * H + h] + ad[h];
            v = v > 0.f ? v : 0.2f * v;
            den[h] += __expf(v);
        }
    }
#pragma unroll
    for (int o = 16; o; o >>= 1)
#pragma unroll
        for (int h = 0; h < H; h++)
            den[h] += __shfl_xor_sync(0xffffffffu, den[h], o);

    float inv_den_l = 0.f, ad_l = 0.f;
    if (lane < H) {
        ad_l = adst[d * H + lane];
#pragma unroll
        for (int h = 0; h < H; h++)
            if (lane == h) inv_den_l = 1.f / den[h];
    }

    constexpr int IT = (H * C) / 128;   // chunk it == head it (C==128)
    float4 acc[IT];
#pragma unroll
    for (int it = 0; it < IT; it++) acc[it] = make_float4(0.f, 0.f, 0.f, 0.f);

    for (int i = beg; i < end; ++i) {
        int s = csrc[i];
        float av = 0.f;
        if (lane < H) {
            float v = asrc[s * H + lane] + ad_l;
            v = v > 0.f ? v : 0.2f * v;
            av = __expf(v) * inv_den_l;
        }
        const float4* fs = (const float4*)(feat + (size_t)s * (H * C));
#pragma unroll
        for (int it = 0; it < IT; it++) {
            float a = __shfl_sync(0xffffffffu, av, it);
            float4 v = fs[it * 32 + lane];
            acc[it].x += a * v.x;
            acc[it].y += a * v.y;
            acc[it].z += a * v.z;
            acc[it].w += a * v.w;
        }
    }

    float4* po = (float4*)(out + (size_t)d * (H * C));
    const float4* pb = (const float4*)bias;
#pragma unroll
    for (int it = 0; it < IT; it++) {
        float4 b = pb[it * 32 + lane];
        float4 v = acc[it];
        v.x += b.x; v.y += b.y; v.z += b.z; v.w += b.w;
        if (RELU) {
            v.x = fmaxf(v.x, 0.f); v.y = fmaxf(v.y, 0.f);
            v.z = fmaxf(v.z, 0.f); v.w = fmaxf(v.w, 0.f);
        }
        po[it * 32 + lane] = v;
    }
}

// ---------------- host driver ------------------------------------------------
template <int H, int C, bool RELU>
static void gat_layer(const float* xin, int K, const float* W,
                      const float* att_s, const float* att_d, const float* bias,
                      const int* offs, const int* csrc,
                      float* hfeat, float* asrc, float* adst, float* out) {
    int N = N_NODES;
    int F = H * C;

    dim3 gg(F / 128, (N + 127) / 128);
    gemm_tf32_attn_kernel<<<gg, 256>>>(xin, W, hfeat, N, K, F,
                                       att_s, att_d, asrc, adst, H);

    long long t = (long long)N * 32;
    agg_kernel<H, C, RELU><<<(int)((t + 255) / 256), 256>>>(
        offs, csrc, asrc, adst, hfeat, bias, out, N);
}

extern "C" void kernel_launch(void* const* d_in, const int* in_sizes, int n_in,
                              void* d_out, int out_size) {
    const float* x   = (const float*)d_in[0];
    const int*   ei  = (const int*)d_in[1];   // int32 (JAX x64 disabled)
    const float* W1  = (const float*)d_in[2];
    const float* as1 = (const float*)d_in[3];
    const float* ad1 = (const float*)d_in[4];
    const float* b1  = (const float*)d_in[5];
    const float* W2  = (const float*)d_in[6];
    const float* as2 = (const float*)d_in[7];
    const float* ad2 = (const float*)d_in[8];
    const float* b2  = (const float*)d_in[9];
    const float* W3  = (const float*)d_in[10];
    const float* as3 = (const float*)d_in[11];
    const float* ad3 = (const float*)d_in[12];
    const float* b3  = (const float*)d_in[13];

    int E = in_sizes[1] / 2;
    int ETot = E + N_NODES;

    float *hA, *hB, *asrc, *adst;
    int *deg, *cursor, *offs, *csrc;
    cudaGetSymbolAddress((void**)&hA,     g_hA);
    cudaGetSymbolAddress((void**)&hB,     g_hB);
    cudaGetSymbolAddress((void**)&asrc,   g_asrc);
    cudaGetSymbolAddress((void**)&adst,   g_adst);
    cudaGetSymbolAddress((void**)&deg,    g_deg);
    cudaGetSymbolAddress((void**)&cursor, g_cursor);
    cudaGetSymbolAddress((void**)&offs,   g_offs);
    cudaGetSymbolAddress((void**)&csrc,   g_csrc);

    // ---- build CSR (dst-indexed) once ----
    cudaMemsetAsync(deg, 0, N_NODES * sizeof(int));
    cudaMemsetAsync(cursor, 0, N_NODES * sizeof(int));
    int eb = (ETot + 255) / 256;
    deg_kernel<<<eb, 256>>>(ei, E, ETot, deg);
    scan_kernel<<<1, 1024>>>(deg, offs, N_NODES);
    fill_kernel<<<eb, 256>>>(ei, E, ETot, offs, cursor, csrc);

    // ---- 3 GAT layers ----
    gat_layer<HEADS, CH, true>(x,  F_IN,  W1, as1, ad1, b1, offs, csrc, hA, asrc, adst, hB);
    gat_layer<HEADS, CH, true>(hB, D_HID, W2, as2, ad2, b2, offs, csrc, hA, asrc, adst, hB);
    gat_layer<1, D_OUT, false>(hB, D_HID, W3, as3, ad3, b3, offs, csrc, hA, asrc, adst, (float*)d_out);
}

// round 7
// speedup vs baseline: 3.5765x; 1.0005x over previous
#include <cuda_runtime.h>
#include <math.h>
#include <stdint.h>

#define N_NODES 30000
#define F_IN    256
#define HEADS   4
#define CH      128
#define D_HID   (HEADS * CH)   // 512
#define D_OUT   128
#define E_MAX   480000
#define ET_MAX  (E_MAX + N_NODES)  // 510000

// ---------------- scratch (device globals; no allocations allowed) ----------
__device__ float g_hA[(size_t)N_NODES * D_HID];
__device__ float g_hB[(size_t)N_NODES * D_HID];
__device__ float g_asrc[N_NODES * HEADS];
__device__ float g_adst[N_NODES * HEADS];
__device__ float g_ex[(size_t)ET_MAX * HEADS];   // per-edge exp scratch
__device__ int   g_deg[N_NODES];
__device__ int   g_cursor[N_NODES];
__device__ int   g_offs[N_NODES + 1];
__device__ int   g_csrc[ET_MAX];

// ---------------- helpers ---------------------------------------------------
__device__ __forceinline__ void edge_sd(int e, const int* __restrict__ ei,
                                        int E, int& s, int& d) {
    if (e < E) { s = ei[e]; d = ei[E + e]; }
    else       { s = d = e - E; }   // self-loops appended
}

__device__ __forceinline__ uint32_t f2tf(float f) {
    uint32_t u;
    asm("cvt.rna.tf32.f32 %0, %1;" : "=r"(u) : "f"(f));
    return u;
}

__device__ __forceinline__ void mma_tf32(float* c, const uint32_t* a, const uint32_t* b) {
    asm volatile(
        "mma.sync.aligned.m16n8k8.row.col.f32.tf32.tf32.f32 "
        "{%0,%1,%2,%3}, {%4,%5,%6,%7}, {%8,%9}, {%0,%1,%2,%3};"
        : "+f"(c[0]), "+f"(c[1]), "+f"(c[2]), "+f"(c[3])
        : "r"(a[0]), "r"(a[1]), "r"(a[2]), "r"(a[3]), "r"(b[0]), "r"(b[1]));
}

// ---------------- tf32 tensor-core GEMM with fused attention epilogue --------
__global__ __launch_bounds__(256, 2)
void gemm_tf32_attn_kernel(const float* __restrict__ A, const float* __restrict__ B,
                           float* __restrict__ C, int M, int K, int N,
                           const float* __restrict__ att_s,
                           const float* __restrict__ att_d,
                           float* __restrict__ asrc, float* __restrict__ adst,
                           int H) {
    constexpr int BM = 128, BN = 128, BK = 32;
    constexpr int AP = BK + 4;
    constexpr int BP = BN + 8;
    __shared__ uint32_t As[BM * AP];
    __shared__ uint32_t Bs[BK * BP];
    __shared__ float s_as[BM];
    __shared__ float s_ad[BM];

    int tid  = threadIdx.x;
    int lane = tid & 31;
    int warp = tid >> 5;
    int warpM = warp & 3;
    int warpN = warp >> 2;
    int bm = blockIdx.y * BM;
    int bn = blockIdx.x * BN;
    int head = blockIdx.x;           // BN == C == 128

    float acc[2][8][4];
#pragma unroll
    for (int mt = 0; mt < 2; mt++)
#pragma unroll
        for (int nt = 0; nt < 8; nt++)
#pragma unroll
            for (int i = 0; i < 4; i++) acc[mt][nt][i] = 0.f;

    for (int k0 = 0; k0 < K; k0 += BK) {
#pragma unroll
        for (int i = 0; i < 4; i++) {
            int lin = tid + i * 256;
            int r = lin >> 3, q = lin & 7;
            float4 v = make_float4(0.f, 0.f, 0.f, 0.f);
            if (bm + r < M)
                v = *(const float4*)&A[(size_t)(bm + r) * K + k0 + q * 4];
            uint4 u = make_uint4(f2tf(v.x), f2tf(v.y), f2tf(v.z), f2tf(v.w));
            *(uint4*)&As[r * AP + q * 4] = u;
        }
#pragma unroll
        for (int i = 0; i < 4; i++) {
            int lin = tid + i * 256;
            int r = lin >> 5, q = lin & 31;
            float4 v = *(const float4*)&B[(size_t)(k0 + r) * N + bn + q * 4];
            uint4 u = make_uint4(f2tf(v.x), f2tf(v.y), f2tf(v.z), f2tf(v.w));
            *(uint4*)&Bs[r * BP + q * 4] = u;
        }
        __syncthreads();

#pragma unroll
        for (int kk = 0; kk < BK / 8; kk++) {
            int kb = kk * 8;
            uint32_t af[2][4], bf[8][2];
            int ar = warpM * 32 + (lane >> 2);
            int ac = kb + (lane & 3);
#pragma unroll
            for (int mt = 0; mt < 2; mt++) {
                int r = ar + mt * 16;
                af[mt][0] = As[r * AP + ac];
                af[mt][1] = As[(r + 8) * AP + ac];
                af[mt][2] = As[r * AP + ac + 4];
                af[mt][3] = As[(r + 8) * AP + ac + 4];
            }
            int br = kb + (lane & 3);
            int bc = warpN * 64 + (lane >> 2);
#pragma unroll
            for (int nt = 0; nt < 8; nt++) {
                bf[nt][0] = Bs[br * BP + bc + nt * 8];
                bf[nt][1] = Bs[(br + 4) * BP + bc + nt * 8];
            }
#pragma unroll
            for (int mt = 0; mt < 2; mt++)
#pragma unroll
                for (int nt = 0; nt < 8; nt++)
                    mma_tf32(acc[mt][nt], af[mt], bf[nt]);
        }
        __syncthreads();
    }

    // ---- store C ----
#pragma unroll
    for (int mt = 0; mt < 2; mt++) {
        int r0 = bm + warpM * 32 + mt * 16 + (lane >> 2);
#pragma unroll
        for (int nt = 0; nt < 8; nt++) {
            int c0 = bn + warpN * 64 + nt * 8 + (lane & 3) * 2;
            if (r0 < M)
                *(float2*)&C[(size_t)r0 * N + c0] =
                    make_float2(acc[mt][nt][0], acc[mt][nt][1]);
            if (r0 + 8 < M)
                *(float2*)&C[(size_t)(r0 + 8) * N + c0] =
                    make_float2(acc[mt][nt][2], acc[mt][nt][3]);
        }
    }

    // ---- fused attention dots ----
    if (tid < BM) { s_as[tid] = 0.f; s_ad[tid] = 0.f; }
    __syncthreads();

    float ps[2][2], pd[2][2];
#pragma unroll
    for (int mt = 0; mt < 2; mt++)
#pragma unroll
        for (int hh = 0; hh < 2; hh++) { ps[mt][hh] = 0.f; pd[mt][hh] = 0.f; }

#pragma unroll
    for (int nt = 0; nt < 8; nt++) {
        int cl = warpN * 64 + nt * 8 + (lane & 3) * 2;
        float a0 = att_s[head * 128 + cl], a1 = att_s[head * 128 + cl + 1];
        float d0 = att_d[head * 128 + cl], d1 = att_d[head * 128 + cl + 1];
#pragma unroll
        for (int mt = 0; mt < 2; mt++) {
            ps[mt][0] += acc[mt][nt][0] * a0 + acc[mt][nt][1] * a1;
            pd[mt][0] += acc[mt][nt][0] * d0 + acc[mt][nt][1] * d1;
            ps[mt][1] += acc[mt][nt][2] * a0 + acc[mt][nt][3] * a1;
            pd[mt][1] += acc[mt][nt][2] * d0 + acc[mt][nt][3] * d1;
        }
    }
#pragma unroll
    for (int o = 1; o <= 2; o <<= 1)
#pragma unroll
        for (int mt = 0; mt < 2; mt++)
#pragma unroll
            for (int hh = 0; hh < 2; hh++) {
                ps[mt][hh] += __shfl_xor_sync(0xffffffffu, ps[mt][hh], o);
                pd[mt][hh] += __shfl_xor_sync(0xffffffffu, pd[mt][hh], o);
            }
    if ((lane & 3) == 0) {
#pragma unroll
        for (int mt = 0; mt < 2; mt++)
#pragma unroll
            for (int hh = 0; hh < 2; hh++) {
                int r = warpM * 32 + mt * 16 + hh * 8 + (lane >> 2);
                atomicAdd(&s_as[r], ps[mt][hh]);
                atomicAdd(&s_ad[r], pd[mt][hh]);
            }
    }
    __syncthreads();
    if (tid < BM && bm + tid < M) {
        asrc[(bm + tid) * H + head] = s_as[tid];
        adst[(bm + tid) * H + head] = s_ad[tid];
    }
}

// ---------------- CSR build --------------------------------------------------
__global__ void deg_kernel(const int* __restrict__ ei, int E, int ETot,
                           int* __restrict__ deg) {
    int e = blockIdx.x * blockDim.x + threadIdx.x;
    if (e >= ETot) return;
    int s, d; edge_sd(e, ei, E, s, d);
    (void)s;
    atomicAdd(&deg[d], 1);
}

__global__ __launch_bounds__(1024)
void scan_kernel(const int* __restrict__ deg, int* __restrict__ offs, int N) {
    __shared__ int sums[1024];
    int tid = threadIdx.x;
    int chunk = (N + 1023) / 1024;
    int base = tid * chunk;
    int s = 0;
    for (int i = 0; i < chunk; i++) {
        int idx = base + i;
        if (idx < N) s += deg[idx];
    }
    sums[tid] = s;
    __syncthreads();
    for (int off = 1; off < 1024; off <<= 1) {
        int v = (tid >= off) ? sums[tid - off] : 0;
        __syncthreads();
        sums[tid] += v;
        __syncthreads();
    }
    int run = (tid == 0) ? 0 : sums[tid - 1];
    for (int i = 0; i < chunk; i++) {
        int idx = base + i;
        if (idx < N) { offs[idx] = run; run += deg[idx]; }
    }
    if (tid == 1023) offs[N] = run;
}

__global__ void fill_kernel(const int* __restrict__ ei, int E, int ETot,
                            const int* __restrict__ offs,
                            int* __restrict__ cursor, int* __restrict__ csrc) {
    int e = blockIdx.x * blockDim.x + threadIdx.x;
    if (e >= ETot) return;
    int s, d; edge_sd(e, ei, E, s, d);
    int pos = atomicAdd(&cursor[d], 1);
    csrc[offs[d] + pos] = s;
}

// ---------------- fused softmax + aggregation + bias + relu ------------------
// One warp per dst. Pass 1 computes per-edge exps (lane-parallel), stores them
// to global scratch, accumulates denominator. Pass 2 processes 32-edge chunks:
// each lane rescales its own stored exps (same thread wrote them) into smem
// alpha, then a 2-edge-unrolled gather loop accumulates alpha*h[src] in regs.
// Epilogue: bias (+relu), single store per row. No atomics, no exp recompute.
template <int H, int C, bool RELU>
__global__ __launch_bounds__(256)
void agg_kernel(const int* __restrict__ offs, const int* __restrict__ csrc,
                const float* __restrict__ asrc, const float* __restrict__ adst,
                const float* __restrict__ feat, const float* __restrict__ bias,
                float* __restrict__ out, float* __restrict__ exs, int N) {
    constexpr int WPB = 8;
    __shared__ float s_alpha[WPB][H * 32];
    __shared__ int   s_src[WPB][32];

    int wid  = threadIdx.x >> 5;
    int lane = threadIdx.x & 31;
    int d = (blockIdx.x * blockDim.x + threadIdx.x) >> 5;
    if (d >= N) return;
    int beg = offs[d], end = offs[d + 1];

    float ad[H];
#pragma unroll
    for (int h = 0; h < H; h++) ad[h] = adst[d * H + h];

    // ---- pass 1: exps + denominator (scores O(1): no max subtraction) ----
    float den[H];
#pragma unroll
    for (int h = 0; h < H; h++) den[h] = 0.f;
    for (int i = beg + lane; i < end; i += 32) {
        int s = csrc[i];
        float ex[H];
#pragma unroll
        for (int h = 0; h < H; h++) {
            float v = asrc[s * H + h] + ad[h];
            v = v > 0.f ? v : 0.2f * v;
            ex[h] = __expf(v);
            den[h] += ex[h];
        }
        if (H == 4)
            *(float4*)&exs[(size_t)i * 4] = make_float4(ex[0], ex[1], ex[2], ex[3]);
        else
            exs[i] = ex[0];
    }
#pragma unroll
    for (int o = 16; o; o >>= 1)
#pragma unroll
        for (int h = 0; h < H; h++)
            den[h] += __shfl_xor_sync(0xffffffffu, den[h], o);
    float inv[H];
#pragma unroll
    for (int h = 0; h < H; h++) inv[h] = 1.f / den[h];

    // ---- pass 2: chunked gather ----
    constexpr int IT = (H * C) / 128;   // 4 (H=4) or 1 (H=1)
    float4 acc[IT];
#pragma unroll
    for (int it = 0; it < IT; it++) acc[it] = make_float4(0.f, 0.f, 0.f, 0.f);

    for (int base = beg; base < end; base += 32) {
        int cnt = min(32, end - base);
        if (lane < cnt) {
            int i = base + lane;           // same edge this lane wrote in pass 1
            s_src[wid][lane] = csrc[i];
            if (H == 4) {
                float4 ex = *(const float4*)&exs[(size_t)i * 4];
                s_alpha[wid][0 * 32 + lane] = ex.x * inv[0];
                s_alpha[wid][1 * 32 + lane] = ex.y * inv[1 % H];
                s_alpha[wid][2 * 32 + lane] = ex.z * inv[2 % H];
                s_alpha[wid][3 * 32 + lane] = ex.w * inv[3 % H];
            } else {
                s_alpha[wid][lane] = exs[base + lane] * inv[0];
            }
        }
        __syncwarp();
        int j = 0;
        for (; j + 1 < cnt; j += 2) {
            int s0 = s_src[wid][j], s1 = s_src[wid][j + 1];
            const float4* f0 = (const float4*)(feat + (size_t)s0 * (H * C));
            const float4* f1 = (const float4*)(feat + (size_t)s1 * (H * C));
            float4 v0[IT], v1[IT];
#pragma unroll
            for (int it = 0; it < IT; it++) v0[it] = f0[it * 32 + lane];
#pragma unroll
            for (int it = 0; it < IT; it++) v1[it] = f1[it * 32 + lane];
#pragma unroll
            for (int it = 0; it < IT; it++) {
                float a0 = s_alpha[wid][it * 32 + j];
                float a1 = s_alpha[wid][it * 32 + j + 1];
                acc[it].x += a0 * v0[it].x + a1 * v1[it].x;
                acc[it].y += a0 * v0[it].y + a1 * v1[it].y;
                acc[it].z += a0 * v0[it].z + a1 * v1[it].z;
                acc[it].w += a0 * v0[it].w + a1 * v1[it].w;
            }
        }
        if (j < cnt) {
            int s0 = s_src[wid][j];
            const float4* f0 = (const float4*)(feat + (size_t)s0 * (H * C));
#pragma unroll
            for (int it = 0; it < IT; it++) {
                float a0 = s_alpha[wid][it * 32 + j];
                float4 v = f0[it * 32 + lane];
                acc[it].x += a0 * v.x;
                acc[it].y += a0 * v.y;
                acc[it].z += a0 * v.z;
                acc[it].w += a0 * v.w;
            }
        }
        __syncwarp();
    }

    float4* po = (float4*)(out + (size_t)d * (H * C));
    const float4* pb = (const float4*)bias;
#pragma unroll
    for (int it = 0; it < IT; it++) {
        float4 b = pb[it * 32 + lane];
        float4 v = acc[it];
        v.x += b.x; v.y += b.y; v.z += b.z; v.w += b.w;
        if (RELU) {
            v.x = fmaxf(v.x, 0.f); v.y = fmaxf(v.y, 0.f);
            v.z = fmaxf(v.z, 0.f); v.w = fmaxf(v.w, 0.f);
        }
        po[it * 32 + lane] = v;
    }
}

// ---------------- host driver ------------------------------------------------
template <int H, int C, bool RELU>
static void gat_layer(const float* xin, int K, const float* W,
                      const float* att_s, const float* att_d, const float* bias,
                      const int* offs, const int* csrc,
                      float* hfeat, float* asrc, float* adst, float* exs,
                      float* out) {
    int N = N_NODES;
    int F = H * C;

    dim3 gg(F / 128, (N + 127) / 128);
    gemm_tf32_attn_kernel<<<gg, 256>>>(xin, W, hfeat, N, K, F,
                                       att_s, att_d, asrc, adst, H);

    long long t = (long long)N * 32;
    agg_kernel<H, C, RELU><<<(int)((t + 255) / 256), 256>>>(
        offs, csrc, asrc, adst, hfeat, bias, out, exs, N);
}

extern "C" void kernel_launch(void* const* d_in, const int* in_sizes, int n_in,
                              void* d_out, int out_size) {
    const float* x   = (const float*)d_in[0];
    const int*   ei  = (const int*)d_in[1];   // int32 (JAX x64 disabled)
    const float* W1  = (const float*)d_in[2];
    const float* as1 = (const float*)d_in[3];
    const float* ad1 = (const float*)d_in[4];
    const float* b1  = (const float*)d_in[5];
    const float* W2  = (const float*)d_in[6];
    const float* as2 = (const float*)d_in[7];
    const float* ad2 = (const float*)d_in[8];
    const float* b2  = (const float*)d_in[9];
    const float* W3  = (const float*)d_in[10];
    const float* as3 = (const float*)d_in[11];
    const float* ad3 = (const float*)d_in[12];
    const float* b3  = (const float*)d_in[13];

    int E = in_sizes[1] / 2;
    int ETot = E + N_NODES;

    float *hA, *hB, *asrc, *adst, *exs;
    int *deg, *cursor, *offs, *csrc;
    cudaGetSymbolAddress((void**)&hA,     g_hA);
    cudaGetSymbolAddress((void**)&hB,     g_hB);
    cudaGetSymbolAddress((void**)&asrc,   g_asrc);
    cudaGetSymbolAddress((void**)&adst,   g_adst);
    cudaGetSymbolAddress((void**)&exs,    g_ex);
    cudaGetSymbolAddress((void**)&deg,    g_deg);
    cudaGetSymbolAddress((void**)&cursor, g_cursor);
    cudaGetSymbolAddress((void**)&offs,   g_offs);
    cudaGetSymbolAddress((void**)&csrc,   g_csrc);

    // ---- build CSR (dst-indexed) once ----
    cudaMemsetAsync(deg, 0, N_NODES * sizeof(int));
    cudaMemsetAsync(cursor, 0, N_NODES * sizeof(int));
    int eb = (ETot + 255) / 256;
    deg_kernel<<<eb, 256>>>(ei, E, ETot, deg);
    scan_kernel<<<1, 1024>>>(deg, offs, N_NODES);
    fill_kernel<<<eb, 256>>>(ei, E, ETot, offs, cursor, csrc);

    // ---- 3 GAT layers ----
    gat_layer<HEADS, CH, true>(x,  F_IN,  W1, as1, ad1, b1, offs, csrc, hA, asrc, adst, exs, hB);
    gat_layer<HEADS, CH, true>(hB, D_HID, W2, as2, ad2, b2, offs, csrc, hA, asrc, adst, exs, hB);
    gat_layer<1, D_OUT, false>(hB, D_HID, W3, as3, ad3, b3, offs, csrc, hA, asrc, adst, exs, (float*)d_out);
}

// round 8
// speedup vs baseline: 3.8049x; 1.0639x over previous
#include <cuda_runtime.h>
#include <math.h>
#include <stdint.h>

#define N_NODES 30000
#define F_IN    256
#define HEADS   4
#define CH      128
#define D_HID   (HEADS * CH)   // 512
#define D_OUT   128
#define E_MAX   480000
#define ET_MAX  (E_MAX + N_NODES)  // 510000

// ---------------- scratch (device globals; no allocations allowed) ----------
__device__ float g_hA[(size_t)N_NODES * D_HID];
__device__ float g_hB[(size_t)N_NODES * D_HID];
__device__ float g_asrc[N_NODES * HEADS];
__device__ float g_adst[N_NODES * HEADS];
__device__ float g_ex[(size_t)ET_MAX * HEADS];
__device__ int   g_deg[N_NODES];
__device__ int   g_cursor[N_NODES];
__device__ int   g_offs[N_NODES + 1];
__device__ int   g_csrc[ET_MAX];

// ---------------- helpers ---------------------------------------------------
__device__ __forceinline__ void edge_sd(int e, const int* __restrict__ ei,
                                        int E, int& s, int& d) {
    if (e < E) { s = ei[e]; d = ei[E + e]; }
    else       { s = d = e - E; }   // self-loops appended
}

__device__ __forceinline__ uint32_t f2tf(float f) {
    uint32_t u;
    asm("cvt.rna.tf32.f32 %0, %1;" : "=r"(u) : "f"(f));
    return u;
}

__device__ __forceinline__ void mma_tf32(float* c, const uint32_t* a, const uint32_t* b) {
    asm volatile(
        "mma.sync.aligned.m16n8k8.row.col.f32.tf32.tf32.f32 "
        "{%0,%1,%2,%3}, {%4,%5,%6,%7}, {%8,%9}, {%0,%1,%2,%3};"
        : "+f"(c[0]), "+f"(c[1]), "+f"(c[2]), "+f"(c[3])
        : "r"(a[0]), "r"(a[1]), "r"(a[2]), "r"(a[3]), "r"(b[0]), "r"(b[1]));
}

__device__ __forceinline__ void cp16(uint32_t dst, const void* src, int bytes) {
    asm volatile("cp.async.cg.shared.global [%0], [%1], 16, %2;"
                 :: "r"(dst), "l"(src), "r"(bytes));
}
__device__ __forceinline__ void cp_commit() {
    asm volatile("cp.async.commit_group;");
}
template <int N>
__device__ __forceinline__ void cp_wait() {
    asm volatile("cp.async.wait_group %0;" :: "n"(N));
}

// ---------------- tf32 GEMM, 2-stage cp.async pipeline, fused attn epilogue --
// C[M,N] = A[M,K] @ B[K,N]. BN == 128 == head width, blockIdx.x == head.
// Dynamic smem: 2 stages of (A tile 128x32 pad36, B tile 32x128 pad136) fp32.
__global__ __launch_bounds__(256, 2)
void gemm_tf32_attn_kernel(const float* __restrict__ A, const float* __restrict__ B,
                           float* __restrict__ C, int M, int K, int N,
                           const float* __restrict__ att_s,
                           const float* __restrict__ att_d,
                           float* __restrict__ asrc, float* __restrict__ adst,
                           int H) {
    constexpr int BM = 128, BN = 128, BK = 32;
    constexpr int AP = BK + 4;     // 36: A frag banks 4r+c distinct
    constexpr int BP = BN + 8;     // 136: B frag banks 8k+g distinct
    constexpr int ASZ = BM * AP;   // 4608 floats
    constexpr int BSZ = BK * BP;   // 4352 floats

    extern __shared__ float smem[];
    float* Asm = smem;                 // 2 stages: [2][ASZ]
    float* Bsm = smem + 2 * ASZ;       // 2 stages: [2][BSZ]
    __shared__ float s_as[BM];
    __shared__ float s_ad[BM];

    int tid  = threadIdx.x;
    int lane = tid & 31;
    int warp = tid >> 5;
    int warpM = warp & 3;
    int warpN = warp >> 2;
    int bm = blockIdx.y * BM;
    int bn = blockIdx.x * BN;
    int head = blockIdx.x;             // BN == C == 128

    uint32_t asm_base = (uint32_t)__cvta_generic_to_shared(Asm);
    uint32_t bsm_base = (uint32_t)__cvta_generic_to_shared(Bsm);

    // per-thread copy coordinates (4 x 16B each for A and B)
    int ar4[4], aq4[4], br4[4], bq4[4];
#pragma unroll
    for (int i = 0; i < 4; i++) {
        int lin = tid + i * 256;
        ar4[i] = lin >> 3;  aq4[i] = lin & 7;
        br4[i] = lin >> 5;  bq4[i] = lin & 31;
    }

    auto issue_tile = [&](int stage, int k0) {
        uint32_t ad_ = asm_base + (uint32_t)(stage * ASZ) * 4u;
        uint32_t bd_ = bsm_base + (uint32_t)(stage * BSZ) * 4u;
#pragma unroll
        for (int i = 0; i < 4; i++) {
            int r = ar4[i], q = aq4[i];
            const float* src = &A[(size_t)(bm + r) * K + k0 + q * 4];
            cp16(ad_ + (uint32_t)(r * AP + q * 4) * 4u, src, (bm + r < M) ? 16 : 0);
        }
#pragma unroll
        for (int i = 0; i < 4; i++) {
            int r = br4[i], q = bq4[i];
            const float* src = &B[(size_t)(k0 + r) * N + bn + q * 4];
            cp16(bd_ + (uint32_t)(r * BP + q * 4) * 4u, src, 16);
        }
        cp_commit();
    };

    float acc[2][8][4];
#pragma unroll
    for (int mt = 0; mt < 2; mt++)
#pragma unroll
        for (int nt = 0; nt < 8; nt++)
#pragma unroll
            for (int i = 0; i < 4; i++) acc[mt][nt][i] = 0.f;

    int nk = K / BK;
    issue_tile(0, 0);

    for (int t = 0; t < nk; ++t) {
        int st = t & 1;
        if (t + 1 < nk) {
            issue_tile((t + 1) & 1, (t + 1) * BK);
            cp_wait<1>();
        } else {
            cp_wait<0>();
        }
        __syncthreads();

        const float* As = Asm + st * ASZ;
        const float* Bs = Bsm + st * BSZ;
#pragma unroll
        for (int kk = 0; kk < BK / 8; kk++) {
            int kb = kk * 8;
            uint32_t af[2][4], bf[8][2];
            int ar = warpM * 32 + (lane >> 2);
            int ac = kb + (lane & 3);
#pragma unroll
            for (int mt = 0; mt < 2; mt++) {
                int r = ar + mt * 16;
                af[mt][0] = f2tf(As[r * AP + ac]);
                af[mt][1] = f2tf(As[(r + 8) * AP + ac]);
                af[mt][2] = f2tf(As[r * AP + ac + 4]);
                af[mt][3] = f2tf(As[(r + 8) * AP + ac + 4]);
            }
            int br = kb + (lane & 3);
            int bc = warpN * 64 + (lane >> 2);
#pragma unroll
            for (int nt = 0; nt < 8; nt++) {
                bf[nt][0] = f2tf(Bs[br * BP + bc + nt * 8]);
                bf[nt][1] = f2tf(Bs[(br + 4) * BP + bc + nt * 8]);
            }
#pragma unroll
            for (int mt = 0; mt < 2; mt++)
#pragma unroll
                for (int nt = 0; nt < 8; nt++)
                    mma_tf32(acc[mt][nt], af[mt], bf[nt]);
        }
        __syncthreads();
    }

    // ---- store C ----
#pragma unroll
    for (int mt = 0; mt < 2; mt++) {
        int r0 = bm + warpM * 32 + mt * 16 + (lane >> 2);
#pragma unroll
        for (int nt = 0; nt < 8; nt++) {
            int c0 = bn + warpN * 64 + nt * 8 + (lane & 3) * 2;
            if (r0 < M)
                *(float2*)&C[(size_t)r0 * N + c0] =
                    make_float2(acc[mt][nt][0], acc[mt][nt][1]);
            if (r0 + 8 < M)
                *(float2*)&C[(size_t)(r0 + 8) * N + c0] =
                    make_float2(acc[mt][nt][2], acc[mt][nt][3]);
        }
    }

    // ---- fused attention dots ----
    if (tid < BM) { s_as[tid] = 0.f; s_ad[tid] = 0.f; }
    __syncthreads();

    float ps[2][2], pd[2][2];
#pragma unroll
    for (int mt = 0; mt < 2; mt++)
#pragma unroll
        for (int hh = 0; hh < 2; hh++) { ps[mt][hh] = 0.f; pd[mt][hh] = 0.f; }

#pragma unroll
    for (int nt = 0; nt < 8; nt++) {
        int cl = warpN * 64 + nt * 8 + (lane & 3) * 2;
        float a0 = att_s[head * 128 + cl], a1 = att_s[head * 128 + cl + 1];
        float d0 = att_d[head * 128 + cl], d1 = att_d[head * 128 + cl + 1];
#pragma unroll
        for (int mt = 0; mt < 2; mt++) {
            ps[mt][0] += acc[mt][nt][0] * a0 + acc[mt][nt][1] * a1;
            pd[mt][0] += acc[mt][nt][0] * d0 + acc[mt][nt][1] * d1;
            ps[mt][1] += acc[mt][nt][2] * a0 + acc[mt][nt][3] * a1;
            pd[mt][1] += acc[mt][nt][2] * d0 + acc[mt][nt][3] * d1;
        }
    }
#pragma unroll
    for (int o = 1; o <= 2; o <<= 1)
#pragma unroll
        for (int mt = 0; mt < 2; mt++)
#pragma unroll
            for (int hh = 0; hh < 2; hh++) {
                ps[mt][hh] += __shfl_xor_sync(0xffffffffu, ps[mt][hh], o);
                pd[mt][hh] += __shfl_xor_sync(0xffffffffu, pd[mt][hh], o);
            }
    if ((lane & 3) == 0) {
#pragma unroll
        for (int mt = 0; mt < 2; mt++)
#pragma unroll
            for (int hh = 0; hh < 2; hh++) {
                int r = warpM * 32 + mt * 16 + hh * 8 + (lane >> 2);
                atomicAdd(&s_as[r], ps[mt][hh]);
                atomicAdd(&s_ad[r], pd[mt][hh]);
            }
    }
    __syncthreads();
    if (tid < BM && bm + tid < M) {
        asrc[(bm + tid) * H + head] = s_as[tid];
        adst[(bm + tid) * H + head] = s_ad[tid];
    }
}

// ---------------- CSR build --------------------------------------------------
__global__ void deg_kernel(const int* __restrict__ ei, int E, int ETot,
                           int* __restrict__ deg) {
    int e = blockIdx.x * blockDim.x + threadIdx.x;
    if (e >= ETot) return;
    int s, d; edge_sd(e, ei, E, s, d);
    (void)s;
    atomicAdd(&deg[d], 1);
}

__global__ __launch_bounds__(1024)
void scan_kernel(const int* __restrict__ deg, int* __restrict__ offs, int N) {
    __shared__ int sums[1024];
    int tid = threadIdx.x;
    int chunk = (N + 1023) / 1024;
    int base = tid * chunk;
    int s = 0;
    for (int i = 0; i < chunk; i++) {
        int idx = base + i;
        if (idx < N) s += deg[idx];
    }
    sums[tid] = s;
    __syncthreads();
    for (int off = 1; off < 1024; off <<= 1) {
        int v = (tid >= off) ? sums[tid - off] : 0;
        __syncthreads();
        sums[tid] += v;
        __syncthreads();
    }
    int run = (tid == 0) ? 0 : sums[tid - 1];
    for (int i = 0; i < chunk; i++) {
        int idx = base + i;
        if (idx < N) { offs[idx] = run; run += deg[idx]; }
    }
    if (tid == 1023) offs[N] = run;
}

__global__ void fill_kernel(const int* __restrict__ ei, int E, int ETot,
                            const int* __restrict__ offs,
                            int* __restrict__ cursor, int* __restrict__ csrc) {
    int e = blockIdx.x * blockDim.x + threadIdx.x;
    if (e >= ETot) return;
    int s, d; edge_sd(e, ei, E, s, d);
    int pos = atomicAdd(&cursor[d], 1);
    csrc[offs[d] + pos] = s;
}

// ---------------- fused softmax + aggregation + bias + relu ------------------
template <int H, int C, bool RELU>
__global__ __launch_bounds__(256)
void agg_kernel(const int* __restrict__ offs, const int* __restrict__ csrc,
                const float* __restrict__ asrc, const float* __restrict__ adst,
                const float* __restrict__ feat, const float* __restrict__ bias,
                float* __restrict__ out, float* __restrict__ exs, int N) {
    constexpr int WPB = 8;
    __shared__ float s_alpha[WPB][H * 32];
    __shared__ int   s_src[WPB][32];

    int wid  = threadIdx.x >> 5;
    int lane = threadIdx.x & 31;
    int d = (blockIdx.x * blockDim.x + threadIdx.x) >> 5;
    if (d >= N) return;
    int beg = offs[d], end = offs[d + 1];

    float ad[H];
#pragma unroll
    for (int h = 0; h < H; h++) ad[h] = adst[d * H + h];

    float den[H];
#pragma unroll
    for (int h = 0; h < H; h++) den[h] = 0.f;
    for (int i = beg + lane; i < end; i += 32) {
        int s = csrc[i];
        float ex[H];
#pragma unroll
        for (int h = 0; h < H; h++) {
            float v = asrc[s * H + h] + ad[h];
            v = v > 0.f ? v : 0.2f * v;
            ex[h] = __expf(v);
            den[h] += ex[h];
        }
        if (H == 4)
            *(float4*)&exs[(size_t)i * 4] = make_float4(ex[0], ex[1], ex[2], ex[3]);
        else
            exs[i] = ex[0];
    }
#pragma unroll
    for (int o = 16; o; o >>= 1)
#pragma unroll
        for (int h = 0; h < H; h++)
            den[h] += __shfl_xor_sync(0xffffffffu, den[h], o);
    float inv[H];
#pragma unroll
    for (int h = 0; h < H; h++) inv[h] = 1.f / den[h];

    constexpr int IT = (H * C) / 128;
    float4 acc[IT];
#pragma unroll
    for (int it = 0; it < IT; it++) acc[it] = make_float4(0.f, 0.f, 0.f, 0.f);

    for (int base = beg; base < end; base += 32) {
        int cnt = min(32, end - base);
        if (lane < cnt) {
            int i = base + lane;
            s_src[wid][lane] = csrc[i];
            if (H == 4) {
                float4 ex = *(const float4*)&exs[(size_t)i * 4];
                s_alpha[wid][0 * 32 + lane] = ex.x * inv[0];
                s_alpha[wid][1 * 32 + lane] = ex.y * inv[1 % H];
                s_alpha[wid][2 * 32 + lane] = ex.z * inv[2 % H];
                s_alpha[wid][3 * 32 + lane] = ex.w * inv[3 % H];
            } else {
                s_alpha[wid][lane] = exs[base + lane] * inv[0];
            }
        }
        __syncwarp();
        int j = 0;
        for (; j + 1 < cnt; j += 2) {
            int s0 = s_src[wid][j], s1 = s_src[wid][j + 1];
            const float4* f0 = (const float4*)(feat + (size_t)s0 * (H * C));
            const float4* f1 = (const float4*)(feat + (size_t)s1 * (H * C));
            float4 v0[IT], v1[IT];
#pragma unroll
            for (int it = 0; it < IT; it++) v0[it] = f0[it * 32 + lane];
#pragma unroll
            for (int it = 0; it < IT; it++) v1[it] = f1[it * 32 + lane];
#pragma unroll
            for (int it = 0; it < IT; it++) {
                float a0 = s_alpha[wid][it * 32 + j];
                float a1 = s_alpha[wid][it * 32 + j + 1];
                acc[it].x += a0 * v0[it].x + a1 * v1[it].x;
                acc[it].y += a0 * v0[it].y + a1 * v1[it].y;
                acc[it].z += a0 * v0[it].z + a1 * v1[it].z;
                acc[it].w += a0 * v0[it].w + a1 * v1[it].w;
            }
        }
        if (j < cnt) {
            int s0 = s_src[wid][j];
            const float4* f0 = (const float4*)(feat + (size_t)s0 * (H * C));
#pragma unroll
            for (int it = 0; it < IT; it++) {
                float a0 = s_alpha[wid][it * 32 + j];
                float4 v = f0[it * 32 + lane];
                acc[it].x += a0 * v.x;
                acc[it].y += a0 * v.y;
                acc[it].z += a0 * v.z;
                acc[it].w += a0 * v.w;
            }
        }
        __syncwarp();
    }

    float4* po = (float4*)(out + (size_t)d * (H * C));
    const float4* pb = (const float4*)bias;
#pragma unroll
    for (int it = 0; it < IT; it++) {
        float4 b = pb[it * 32 + lane];
        float4 v = acc[it];
        v.x += b.x; v.y += b.y; v.z += b.z; v.w += b.w;
        if (RELU) {
            v.x = fmaxf(v.x, 0.f); v.y = fmaxf(v.y, 0.f);
            v.z = fmaxf(v.z, 0.f); v.w = fmaxf(v.w, 0.f);
        }
        po[it * 32 + lane] = v;
    }
}

// ---------------- host driver ------------------------------------------------
static const int GEMM_SMEM = (2 * 128 * 36 + 2 * 32 * 136) * 4;  // 71680 B

template <int H, int C, bool RELU>
static void gat_layer(const float* xin, int K, const float* W,
                      const float* att_s, const float* att_d, const float* bias,
                      const int* offs, const int* csrc,
                      float* hfeat, float* asrc, float* adst, float* exs,
                      float* out) {
    int N = N_NODES;
    int F = H * C;

    dim3 gg(F / 128, (N + 127) / 128);
    gemm_tf32_attn_kernel<<<gg, 256, GEMM_SMEM>>>(xin, W, hfeat, N, K, F,
                                                  att_s, att_d, asrc, adst, H);

    long long t = (long long)N * 32;
    agg_kernel<H, C, RELU><<<(int)((t + 255) / 256), 256>>>(
        offs, csrc, asrc, adst, hfeat, bias, out, exs, N);
}

extern "C" void kernel_launch(void* const* d_in, const int* in_sizes, int n_in,
                              void* d_out, int out_size) {
    const float* x   = (const float*)d_in[0];
    const int*   ei  = (const int*)d_in[1];   // int32 (JAX x64 disabled)
    const float* W1  = (const float*)d_in[2];
    const float* as1 = (const float*)d_in[3];
    const float* ad1 = (const float*)d_in[4];
    const float* b1  = (const float*)d_in[5];
    const float* W2  = (const float*)d_in[6];
    const float* as2 = (const float*)d_in[7];
    const float* ad2 = (const float*)d_in[8];
    const float* b2  = (const float*)d_in[9];
    const float* W3  = (const float*)d_in[10];
    const float* as3 = (const float*)d_in[11];
    const float* ad3 = (const float*)d_in[12];
    const float* b3  = (const float*)d_in[13];

    // opt-in to >48KB dynamic smem (idempotent host-side config)
    cudaFuncSetAttribute(gemm_tf32_attn_kernel,
                         cudaFuncAttributeMaxDynamicSharedMemorySize, GEMM_SMEM);

    int E = in_sizes[1] / 2;
    int ETot = E + N_NODES;

    float *hA, *hB, *asrc, *adst, *exs;
    int *deg, *cursor, *offs, *csrc;
    cudaGetSymbolAddress((void**)&hA,     g_hA);
    cudaGetSymbolAddress((void**)&hB,     g_hB);
    cudaGetSymbolAddress((void**)&asrc,   g_asrc);
    cudaGetSymbolAddress((void**)&adst,   g_adst);
    cudaGetSymbolAddress((void**)&exs,    g_ex);
    cudaGetSymbolAddress((void**)&deg,    g_deg);
    cudaGetSymbolAddress((void**)&cursor, g_cursor);
    cudaGetSymbolAddress((void**)&offs,   g_offs);
    cudaGetSymbolAddress((void**)&csrc,   g_csrc);

    // ---- build CSR (dst-indexed) once ----
    cudaMemsetAsync(deg, 0, N_NODES * sizeof(int));
    cudaMemsetAsync(cursor, 0, N_NODES * sizeof(int));
    int eb = (ETot + 255) / 256;
    deg_kernel<<<eb, 256>>>(ei, E, ETot, deg);
    scan_kernel<<<1, 1024>>>(deg, offs, N_NODES);
    fill_kernel<<<eb, 256>>>(ei, E, ETot, offs, cursor, csrc);

    // ---- 3 GAT layers ----
    gat_layer<HEADS, CH, true>(x,  F_IN,  W1, as1, ad1, b1, offs, csrc, hA, asrc, adst, exs, hB);
    gat_layer<HEADS, CH, true>(hB, D_HID, W2, as2, ad2, b2, offs, csrc, hA, asrc, adst, exs, hB);
    gat_layer<1, D_OUT, false>(hB, D_HID, W3, as3, ad3, b3, offs, csrc, hA, asrc, adst, exs, (float*)d_out);
}

// round 9
// speedup vs baseline: 4.5914x; 1.2067x over previous
#include <cuda_runtime.h>
#include <cuda_bf16.h>
#include <math.h>
#include <stdint.h>

#define N_NODES 30000
#define F_IN    256
#define HEADS   4
#define CH      128
#define D_HID   (HEADS * CH)   // 512
#define D_OUT   128
#define E_MAX   480000
#define ET_MAX  (E_MAX + N_NODES)  // 510000

// ---------------- scratch (device globals; no allocations allowed) ----------
__device__ float g_Ar[(size_t)N_NODES * D_HID];            // tf32-rounded GEMM A input
__device__ float g_Wr[512 * 512];                          // tf32-rounded weights
__device__ __nv_bfloat16 g_h16[(size_t)N_NODES * D_HID];   // bf16 features for gather
__device__ float g_asrc[N_NODES * HEADS];
__device__ float g_adst[N_NODES * HEADS];
__device__ float g_ex[(size_t)ET_MAX * HEADS];
__device__ int   g_deg[N_NODES];
__device__ int   g_cursor[N_NODES];
__device__ int   g_offs[N_NODES + 1];
__device__ int   g_csrc[ET_MAX];

// ---------------- helpers ---------------------------------------------------
__device__ __forceinline__ void edge_sd(int e, const int* __restrict__ ei,
                                        int E, int& s, int& d) {
    if (e < E) { s = ei[e]; d = ei[E + e]; }
    else       { s = d = e - E; }   // self-loops appended
}

__device__ __forceinline__ uint32_t f2tf(float f) {
    uint32_t u;
    asm("cvt.rna.tf32.f32 %0, %1;" : "=r"(u) : "f"(f));
    return u;
}

__device__ __forceinline__ void mma_tf32(float* c, const uint32_t* a, const uint32_t* b) {
    asm volatile(
        "mma.sync.aligned.m16n8k8.row.col.f32.tf32.tf32.f32 "
        "{%0,%1,%2,%3}, {%4,%5,%6,%7}, {%8,%9}, {%0,%1,%2,%3};"
        : "+f"(c[0]), "+f"(c[1]), "+f"(c[2]), "+f"(c[3])
        : "r"(a[0]), "r"(a[1]), "r"(a[2]), "r"(a[3]), "r"(b[0]), "r"(b[1]));
}

__device__ __forceinline__ void cp16(uint32_t dst, const void* src, int bytes) {
    asm volatile("cp.async.cg.shared.global [%0], [%1], 16, %2;"
                 :: "r"(dst), "l"(src), "r"(bytes));
}
__device__ __forceinline__ void cp_commit() {
    asm volatile("cp.async.commit_group;");
}
template <int N>
__device__ __forceinline__ void cp_wait() {
    asm volatile("cp.async.wait_group %0;" :: "n"(N));
}

// ---------------- tf32 pre-round (rna) ---------------------------------------
__global__ void round_tf32_kernel(const float* __restrict__ in,
                                  float* __restrict__ out, int n4) {
    int i = blockIdx.x * blockDim.x + threadIdx.x;
    if (i >= n4) return;
    float4 v = ((const float4*)in)[i];
    ((float4*)out)[i] = make_float4(__uint_as_float(f2tf(v.x)),
                                    __uint_as_float(f2tf(v.y)),
                                    __uint_as_float(f2tf(v.z)),
                                    __uint_as_float(f2tf(v.w)));
}

// ---------------- tf32 GEMM (pre-rounded operands, raw-bit mma), 2-stage -----
// cp.async pipeline, fused attention epilogue, bf16 feature store.
// C(bf16 h16)[M,N] = A[M,K] @ B[K,N]. BN == 128 == head width, blockIdx.x==head.
__global__ __launch_bounds__(256, 2)
void gemm_tf32_attn_kernel(const float* __restrict__ A, const float* __restrict__ B,
                           __nv_bfloat16* __restrict__ h16, int M, int K, int N,
                           const float* __restrict__ att_s,
                           const float* __restrict__ att_d,
                           float* __restrict__ asrc, float* __restrict__ adst,
                           int H) {
    constexpr int BM = 128, BN = 128, BK = 32;
    constexpr int AP = BK + 4;
    constexpr int BP = BN + 8;
    constexpr int ASZ = BM * AP;
    constexpr int BSZ = BK * BP;

    extern __shared__ float smem[];
    float* Asm = smem;
    float* Bsm = smem + 2 * ASZ;
    __shared__ float s_as[BM];
    __shared__ float s_ad[BM];

    int tid  = threadIdx.x;
    int lane = tid & 31;
    int warp = tid >> 5;
    int warpM = warp & 3;
    int warpN = warp >> 2;
    int bm = blockIdx.y * BM;
    int bn = blockIdx.x * BN;
    int head = blockIdx.x;

    uint32_t asm_base = (uint32_t)__cvta_generic_to_shared(Asm);
    uint32_t bsm_base = (uint32_t)__cvta_generic_to_shared(Bsm);

    int ar4[4], aq4[4], br4[4], bq4[4];
#pragma unroll
    for (int i = 0; i < 4; i++) {
        int lin = tid + i * 256;
        ar4[i] = lin >> 3;  aq4[i] = lin & 7;
        br4[i] = lin >> 5;  bq4[i] = lin & 31;
    }

    auto issue_tile = [&](int stage, int k0) {
        uint32_t ad_ = asm_base + (uint32_t)(stage * ASZ) * 4u;
        uint32_t bd_ = bsm_base + (uint32_t)(stage * BSZ) * 4u;
#pragma unroll
        for (int i = 0; i < 4; i++) {
            int r = ar4[i], q = aq4[i];
            const float* src = &A[(size_t)(bm + r) * K + k0 + q * 4];
            cp16(ad_ + (uint32_t)(r * AP + q * 4) * 4u, src, (bm + r < M) ? 16 : 0);
        }
#pragma unroll
        for (int i = 0; i < 4; i++) {
            int r = br4[i], q = bq4[i];
            const float* src = &B[(size_t)(k0 + r) * N + bn + q * 4];
            cp16(bd_ + (uint32_t)(r * BP + q * 4) * 4u, src, 16);
        }
        cp_commit();
    };

    float acc[2][8][4];
#pragma unroll
    for (int mt = 0; mt < 2; mt++)
#pragma unroll
        for (int nt = 0; nt < 8; nt++)
#pragma unroll
            for (int i = 0; i < 4; i++) acc[mt][nt][i] = 0.f;

    int nk = K / BK;
    issue_tile(0, 0);

    for (int t = 0; t < nk; ++t) {
        int st = t & 1;
        if (t + 1 < nk) {
            issue_tile((t + 1) & 1, (t + 1) * BK);
            cp_wait<1>();
        } else {
            cp_wait<0>();
        }
        __syncthreads();

        const uint32_t* As = (const uint32_t*)(Asm + st * ASZ);
        const uint32_t* Bs = (const uint32_t*)(Bsm + st * BSZ);
#pragma unroll
        for (int kk = 0; kk < BK / 8; kk++) {
            int kb = kk * 8;
            uint32_t af[2][4], bf[8][2];
            int ar = warpM * 32 + (lane >> 2);
            int ac = kb + (lane & 3);
#pragma unroll
            for (int mt = 0; mt < 2; mt++) {
                int r = ar + mt * 16;
                af[mt][0] = As[r * AP + ac];
                af[mt][1] = As[(r + 8) * AP + ac];
                af[mt][2] = As[r * AP + ac + 4];
                af[mt][3] = As[(r + 8) * AP + ac + 4];
            }
            int br = kb + (lane & 3);
            int bc = warpN * 64 + (lane >> 2);
#pragma unroll
            for (int nt = 0; nt < 8; nt++) {
                bf[nt][0] = Bs[br * BP + bc + nt * 8];
                bf[nt][1] = Bs[(br + 4) * BP + bc + nt * 8];
            }
#pragma unroll
            for (int mt = 0; mt < 2; mt++)
#pragma unroll
                for (int nt = 0; nt < 8; nt++)
                    mma_tf32(acc[mt][nt], af[mt], bf[nt]);
        }
        __syncthreads();
    }

    // ---- store bf16 features ----
#pragma unroll
    for (int mt = 0; mt < 2; mt++) {
        int r0 = bm + warpM * 32 + mt * 16 + (lane >> 2);
#pragma unroll
        for (int nt = 0; nt < 8; nt++) {
            int c0 = bn + warpN * 64 + nt * 8 + (lane & 3) * 2;
            if (r0 < M)
                *(__nv_bfloat162*)&h16[(size_t)r0 * N + c0] =
                    __floats2bfloat162_rn(acc[mt][nt][0], acc[mt][nt][1]);
            if (r0 + 8 < M)
                *(__nv_bfloat162*)&h16[(size_t)(r0 + 8) * N + c0] =
                    __floats2bfloat162_rn(acc[mt][nt][2], acc[mt][nt][3]);
        }
    }

    // ---- fused attention dots (fp32 accumulators) ----
    if (tid < BM) { s_as[tid] = 0.f; s_ad[tid] = 0.f; }
    __syncthreads();

    float ps[2][2], pd[2][2];
#pragma unroll
    for (int mt = 0; mt < 2; mt++)
#pragma unroll
        for (int hh = 0; hh < 2; hh++) { ps[mt][hh] = 0.f; pd[mt][hh] = 0.f; }

#pragma unroll
    for (int nt = 0; nt < 8; nt++) {
        int cl = warpN * 64 + nt * 8 + (lane & 3) * 2;
        float a0 = att_s[head * 128 + cl], a1 = att_s[head * 128 + cl + 1];
        float d0 = att_d[head * 128 + cl], d1 = att_d[head * 128 + cl + 1];
#pragma unroll
        for (int mt = 0; mt < 2; mt++) {
            ps[mt][0] += acc[mt][nt][0] * a0 + acc[mt][nt][1] * a1;
            pd[mt][0] += acc[mt][nt][0] * d0 + acc[mt][nt][1] * d1;
            ps[mt][1] += acc[mt][nt][2] * a0 + acc[mt][nt][3] * a1;
            pd[mt][1] += acc[mt][nt][2] * d0 + acc[mt][nt][3] * d1;
        }
    }
#pragma unroll
    for (int o = 1; o <= 2; o <<= 1)
#pragma unroll
        for (int mt = 0; mt < 2; mt++)
#pragma unroll
            for (int hh = 0; hh < 2; hh++) {
                ps[mt][hh] += __shfl_xor_sync(0xffffffffu, ps[mt][hh], o);
                pd[mt][hh] += __shfl_xor_sync(0xffffffffu, pd[mt][hh], o);
            }
    if ((lane & 3) == 0) {
#pragma unroll
        for (int mt = 0; mt < 2; mt++)
#pragma unroll
            for (int hh = 0; hh < 2; hh++) {
                int r = warpM * 32 + mt * 16 + hh * 8 + (lane >> 2);
                atomicAdd(&s_as[r], ps[mt][hh]);
                atomicAdd(&s_ad[r], pd[mt][hh]);
            }
    }
    __syncthreads();
    if (tid < BM && bm + tid < M) {
        asrc[(bm + tid) * H + head] = s_as[tid];
        adst[(bm + tid) * H + head] = s_ad[tid];
    }
}

// ---------------- CSR build --------------------------------------------------
__global__ void deg_kernel(const int* __restrict__ ei, int E, int ETot,
                           int* __restrict__ deg) {
    int e = blockIdx.x * blockDim.x + threadIdx.x;
    if (e >= ETot) return;
    int s, d; edge_sd(e, ei, E, s, d);
    (void)s;
    atomicAdd(&deg[d], 1);
}

__global__ __launch_bounds__(1024)
void scan_kernel(const int* __restrict__ deg, int* __restrict__ offs, int N) {
    __shared__ int sums[1024];
    int tid = threadIdx.x;
    int chunk = (N + 1023) / 1024;
    int base = tid * chunk;
    int s = 0;
    for (int i = 0; i < chunk; i++) {
        int idx = base + i;
        if (idx < N) s += deg[idx];
    }
    sums[tid] = s;
    __syncthreads();
    for (int off = 1; off < 1024; off <<= 1) {
        int v = (tid >= off) ? sums[tid - off] : 0;
        __syncthreads();
        sums[tid] += v;
        __syncthreads();
    }
    int run = (tid == 0) ? 0 : sums[tid - 1];
    for (int i = 0; i < chunk; i++) {
        int idx = base + i;
        if (idx < N) { offs[idx] = run; run += deg[idx]; }
    }
    if (tid == 1023) offs[N] = run;
}

__global__ void fill_kernel(const int* __restrict__ ei, int E, int ETot,
                            const int* __restrict__ offs,
                            int* __restrict__ cursor, int* __restrict__ csrc) {
    int e = blockIdx.x * blockDim.x + threadIdx.x;
    if (e >= ETot) return;
    int s, d; edge_sd(e, ei, E, s, d);
    int pos = atomicAdd(&cursor[d], 1);
    csrc[offs[d] + pos] = s;
}

// ---------------- fused softmax + aggregation + bias + relu ------------------
// bf16 gather, fp32 accumulate. ROUND: store tf32-rounded fp32 (feeds next GEMM).
__device__ __forceinline__ void accum8(float* acc, uint4 u, float a) {
    const __nv_bfloat162* p = (const __nv_bfloat162*)&u;
#pragma unroll
    for (int k = 0; k < 4; k++) {
        float2 f = __bfloat1622float2(p[k]);
        acc[k * 2]     += a * f.x;
        acc[k * 2 + 1] += a * f.y;
    }
}

template <int H, int C, bool RELU, bool ROUND>
__global__ __launch_bounds__(256)
void agg_kernel(const int* __restrict__ offs, const int* __restrict__ csrc,
                const float* __restrict__ asrc, const float* __restrict__ adst,
                const __nv_bfloat16* __restrict__ feat,
                const float* __restrict__ bias,
                float* __restrict__ out, float* __restrict__ exs, int N) {
    constexpr int WPB = 8;
    constexpr int F = H * C;        // 512 or 128
    constexpr int PL = F / 32;      // features per lane: 16 or 4
    __shared__ float s_alpha[WPB][H * 32];
    __shared__ int   s_src[WPB][32];

    int wid  = threadIdx.x >> 5;
    int lane = threadIdx.x & 31;
    int d = (blockIdx.x * blockDim.x + threadIdx.x) >> 5;
    if (d >= N) return;
    int beg = offs[d], end = offs[d + 1];

    float ad[H];
#pragma unroll
    for (int h = 0; h < H; h++) ad[h] = adst[d * H + h];

    // pass 1: exps + denominator (scores O(1): no max subtraction needed)
    float den[H];
#pragma unroll
    for (int h = 0; h < H; h++) den[h] = 0.f;
    for (int i = beg + lane; i < end; i += 32) {
        int s = csrc[i];
        float ex[H];
#pragma unroll
        for (int h = 0; h < H; h++) {
            float v = asrc[s * H + h] + ad[h];
            v = v > 0.f ? v : 0.2f * v;
            ex[h] = __expf(v);
            den[h] += ex[h];
        }
        if (H == 4)
            *(float4*)&exs[(size_t)i * 4] = make_float4(ex[0], ex[1], ex[2], ex[3]);
        else
            exs[i] = ex[0];
    }
#pragma unroll
    for (int o = 16; o; o >>= 1)
#pragma unroll
        for (int h = 0; h < H; h++)
            den[h] += __shfl_xor_sync(0xffffffffu, den[h], o);
    float inv[H];
#pragma unroll
    for (int h = 0; h < H; h++) inv[h] = 1.f / den[h];

    float acc[PL];
#pragma unroll
    for (int p = 0; p < PL; p++) acc[p] = 0.f;

    for (int base = beg; base < end; base += 32) {
        int cnt = min(32, end - base);
        if (lane < cnt) {
            int i = base + lane;
            s_src[wid][lane] = csrc[i];
            if (H == 4) {
                float4 ex = *(const float4*)&exs[(size_t)i * 4];
                s_alpha[wid][0 * 32 + lane] = ex.x * inv[0];
                s_alpha[wid][1 * 32 + lane] = ex.y * inv[1 % H];
                s_alpha[wid][2 * 32 + lane] = ex.z * inv[2 % H];
                s_alpha[wid][3 * 32 + lane] = ex.w * inv[3 % H];
            } else {
                s_alpha[wid][lane] = exs[base + lane] * inv[0];
            }
        }
        __syncwarp();

        if (H == 4) {
            int h0 = lane >> 4;        // head of features [lane*8, +8)
            int h1 = 2 + (lane >> 4);  // head of features [256+lane*8, +8)
            int j = 0;
            for (; j + 1 < cnt; j += 2) {
                const uint4* f0 = (const uint4*)(feat + (size_t)s_src[wid][j] * F);
                const uint4* f1 = (const uint4*)(feat + (size_t)s_src[wid][j + 1] * F);
                uint4 x00 = f0[lane],      x01 = f0[32 + lane];
                uint4 x10 = f1[lane],      x11 = f1[32 + lane];
                float a00 = s_alpha[wid][h0 * 32 + j];
                float a01 = s_alpha[wid][h1 * 32 + j];
                float a10 = s_alpha[wid][h0 * 32 + j + 1];
                float a11 = s_alpha[wid][h1 * 32 + j + 1];
                accum8(acc,     x00, a00);
                accum8(acc + 8, x01, a01);
                accum8(acc,     x10, a10);
                accum8(acc + 8, x11, a11);
            }
            if (j < cnt) {
                const uint4* f0 = (const uint4*)(feat + (size_t)s_src[wid][j] * F);
                uint4 x00 = f0[lane], x01 = f0[32 + lane];
                accum8(acc,     x00, s_alpha[wid][h0 * 32 + j]);
                accum8(acc + 8, x01, s_alpha[wid][h1 * 32 + j]);
            }
        } else {
            int j = 0;
            for (; j + 1 < cnt; j += 2) {
                const uint2* f0 = (const uint2*)(feat + (size_t)s_src[wid][j] * F);
                const uint2* f1 = (const uint2*)(feat + (size_t)s_src[wid][j + 1] * F);
                uint2 x0 = f0[lane], x1 = f1[lane];
                float a0 = s_alpha[wid][j], a1 = s_alpha[wid][j + 1];
                const __nv_bfloat162* p0 = (const __nv_bfloat162*)&x0;
                const __nv_bfloat162* p1 = (const __nv_bfloat162*)&x1;
#pragma unroll
                for (int k = 0; k < 2; k++) {
                    float2 v0 = __bfloat1622float2(p0[k]);
                    float2 v1 = __bfloat1622float2(p1[k]);
                    acc[k * 2]     += a0 * v0.x + a1 * v1.x;
                    acc[k * 2 + 1] += a0 * v0.y + a1 * v1.y;
                }
            }
            if (j < cnt) {
                const uint2* f0 = (const uint2*)(feat + (size_t)s_src[wid][j] * F);
                uint2 x0 = f0[lane];
                float a0 = s_alpha[wid][j];
                const __nv_bfloat162* p0 = (const __nv_bfloat162*)&x0;
#pragma unroll
                for (int k = 0; k < 2; k++) {
                    float2 v0 = __bfloat1622float2(p0[k]);
                    acc[k * 2]     += a0 * v0.x;
                    acc[k * 2 + 1] += a0 * v0.y;
                }
            }
        }
        __syncwarp();
    }

    // epilogue: bias (+relu) (+tf32 round), single store per row
    float* po = out + (size_t)d * F;
    if (H == 4) {
#pragma unroll
        for (int half = 0; half < 2; half++) {
            int bf_ = half * 256 + lane * 8;
#pragma unroll
            for (int q = 0; q < 2; q++) {
                float4 b = *(const float4*)&bias[bf_ + q * 4];
                float4 v;
                v.x = acc[half * 8 + q * 4 + 0] + b.x;
                v.y = acc[half * 8 + q * 4 + 1] + b.y;
                v.z = acc[half * 8 + q * 4 + 2] + b.z;
                v.w = acc[half * 8 + q * 4 + 3] + b.w;
                if (RELU) {
                    v.x = fmaxf(v.x, 0.f); v.y = fmaxf(v.y, 0.f);
                    v.z = fmaxf(v.z, 0.f); v.w = fmaxf(v.w, 0.f);
                }
                if (ROUND) {
                    v.x = __uint_as_float(f2tf(v.x));
                    v.y = __uint_as_float(f2tf(v.y));
                    v.z = __uint_as_float(f2tf(v.z));
                    v.w = __uint_as_float(f2tf(v.w));
                }
                *(float4*)&po[bf_ + q * 4] = v;
            }
        }
    } else {
        float4 b = *(const float4*)&bias[lane * 4];
        float4 v = make_float4(acc[0] + b.x, acc[1] + b.y, acc[2] + b.z, acc[3] + b.w);
        if (RELU) {
            v.x = fmaxf(v.x, 0.f); v.y = fmaxf(v.y, 0.f);
            v.z = fmaxf(v.z, 0.f); v.w = fmaxf(v.w, 0.f);
        }
        if (ROUND) {
            v.x = __uint_as_float(f2tf(v.x));
            v.y = __uint_as_float(f2tf(v.y));
            v.z = __uint_as_float(f2tf(v.z));
            v.w = __uint_as_float(f2tf(v.w));
        }
        *(float4*)&po[lane * 4] = v;
    }
}

// ---------------- host driver ------------------------------------------------
static const int GEMM_SMEM = (2 * 128 * 36 + 2 * 32 * 136) * 4;  // 71680 B

extern "C" void kernel_launch(void* const* d_in, const int* in_sizes, int n_in,
                              void* d_out, int out_size) {
    const float* x   = (const float*)d_in[0];
    const int*   ei  = (const int*)d_in[1];   // int32 (JAX x64 disabled)
    const float* W1  = (const float*)d_in[2];
    const float* as1 = (const float*)d_in[3];
    const float* ad1 = (const float*)d_in[4];
    const float* b1  = (const float*)d_in[5];
    const float* W2  = (const float*)d_in[6];
    const float* as2 = (const float*)d_in[7];
    const float* ad2 = (const float*)d_in[8];
    const float* b2  = (const float*)d_in[9];
    const float* W3  = (const float*)d_in[10];
    const float* as3 = (const float*)d_in[11];
    const float* ad3 = (const float*)d_in[12];
    const float* b3  = (const float*)d_in[13];

    cudaFuncSetAttribute(gemm_tf32_attn_kernel,
                         cudaFuncAttributeMaxDynamicSharedMemorySize, GEMM_SMEM);

    int E = in_sizes[1] / 2;
    int ETot = E + N_NODES;
    int N = N_NODES;

    float *Ar, *Wr, *asrc, *adst, *exs;
    __nv_bfloat16* h16;
    int *deg, *cursor, *offs, *csrc;
    cudaGetSymbolAddress((void**)&Ar,     g_Ar);
    cudaGetSymbolAddress((void**)&Wr,     g_Wr);
    cudaGetSymbolAddress((void**)&h16,    g_h16);
    cudaGetSymbolAddress((void**)&asrc,   g_asrc);
    cudaGetSymbolAddress((void**)&adst,   g_adst);
    cudaGetSymbolAddress((void**)&exs,    g_ex);
    cudaGetSymbolAddress((void**)&deg,    g_deg);
    cudaGetSymbolAddress((void**)&cursor, g_cursor);
    cudaGetSymbolAddress((void**)&offs,   g_offs);
    cudaGetSymbolAddress((void**)&csrc,   g_csrc);

    // ---- build CSR (dst-indexed) once ----
    cudaMemsetAsync(deg, 0, N_NODES * sizeof(int));
    cudaMemsetAsync(cursor, 0, N_NODES * sizeof(int));
    int eb = (ETot + 255) / 256;
    deg_kernel<<<eb, 256>>>(ei, E, ETot, deg);
    scan_kernel<<<1, 1024>>>(deg, offs, N_NODES);
    fill_kernel<<<eb, 256>>>(ei, E, ETot, offs, cursor, csrc);

    long long aggT = (long long)N * 32;
    int aggB = (int)((aggT + 255) / 256);
    dim3 gemm_grid4(4, (N + 127) / 128);
    dim3 gemm_grid1(1, (N + 127) / 128);

    // ---- pre-round x ----
    int n4x = (N_NODES * F_IN) / 4;
    round_tf32_kernel<<<(n4x + 255) / 256, 256>>>(x, Ar, n4x);

    // ---- layer 1: 256 -> 4x128, concat + relu ----
    round_tf32_kernel<<<((F_IN * D_HID) / 4 + 255) / 256, 256>>>(W1, Wr, (F_IN * D_HID) / 4);
    gemm_tf32_attn_kernel<<<gemm_grid4, 256, GEMM_SMEM>>>(
        Ar, Wr, h16, N, F_IN, D_HID, as1, ad1, asrc, adst, HEADS);
    agg_kernel<HEADS, CH, true, true><<<aggB, 256>>>(
        offs, csrc, asrc, adst, h16, b1, Ar, exs, N);

    // ---- layer 2: 512 -> 4x128, concat + relu ----
    round_tf32_kernel<<<((D_HID * D_HID) / 4 + 255) / 256, 256>>>(W2, Wr, (D_HID * D_HID) / 4);
    gemm_tf32_attn_kernel<<<gemm_grid4, 256, GEMM_SMEM>>>(
        Ar, Wr, h16, N, D_HID, D_HID, as2, ad2, asrc, adst, HEADS);
    agg_kernel<HEADS, CH, true, true><<<aggB, 256>>>(
        offs, csrc, asrc, adst, h16, b2, Ar, exs, N);

    // ---- layer 3: 512 -> 1x128, +bias, no relu ----
    round_tf32_kernel<<<((D_HID * D_OUT) / 4 + 255) / 256, 256>>>(W3, Wr, (D_HID * D_OUT) / 4);
    gemm_tf32_attn_kernel<<<gemm_grid1, 256, GEMM_SMEM>>>(
        Ar, Wr, h16, N, D_HID, D_OUT, as3, ad3, asrc, adst, 1);
    agg_kernel<1, D_OUT, false, false><<<aggB, 256>>>(
        offs, csrc, asrc, adst, h16, b3, (float*)d_out, exs, N);
}